// round 3
// baseline (speedup 1.0000x reference)
#include <cuda_runtime.h>
#include <cstdint>

#define B_  2
#define N_  512
#define C_  128
#define H_  8
#define CD_ 16

// ---------------- scratch (device globals: no allocations allowed) ----------
__device__ float g_Q[B_ * N_ * C_];              // pre-scaled by 1/sqrt(CD)=0.25
__device__ float g_K[B_ * N_ * C_];
__device__ float g_V[B_ * N_ * C_];
__device__ float g_S[B_ * H_ * N_ * N_];         // stored TRANSPOSED: [b,h,j,i]

// ---------------- packed f32x2 helpers --------------------------------------
__device__ __forceinline__ void fma2(unsigned long long& acc,
                                     unsigned long long a,
                                     unsigned long long b) {
    asm("fma.rn.f32x2 %0, %1, %2, %0;" : "+l"(acc) : "l"(a), "l"(b));
}
__device__ __forceinline__ unsigned long long pack2(float lo, float hi) {
    unsigned long long r;
    asm("mov.b64 %0, {%1, %2};" : "=l"(r) : "f"(lo), "f"(hi));
    return r;
}
__device__ __forceinline__ float2 unpack2(unsigned long long v) {
    float2 f;
    asm("mov.b64 {%0, %1}, %2;" : "=f"(f.x), "=f"(f.y) : "l"(v));
    return f;
}

// ============================================================================
// Kernel 1: Q/K/V projections.  Q gets the 1/sqrt(CD) factor folded in.
// 98304 threads, each produces 4 outputs of one of {Q,K,V}.
// ============================================================================
__global__ void qkv_kernel(const float* __restrict__ h,
                           const float* __restrict__ Wq,
                           const float* __restrict__ Wk,
                           const float* __restrict__ Wv) {
    int gid = blockIdx.x * blockDim.x + threadIdx.x;   // [0, 98304)
    int row = gid / 96;                                // b*N + n
    int q   = gid % 96;
    int mat = q >> 5;                                  // 0:Q 1:K 2:V
    int d   = (q & 31) * 4;

    const float* W   = (mat == 0) ? Wq : (mat == 1) ? Wk : Wv;
    float*       out = (mat == 0) ? g_Q : (mat == 1) ? g_K : g_V;
    const float* hrow = h + (size_t)row * C_;

    float4 acc = make_float4(0.f, 0.f, 0.f, 0.f);
#pragma unroll 4
    for (int c = 0; c < C_; c++) {
        float  hv = __ldg(hrow + c);
        float4 w  = *(const float4*)(W + (size_t)c * C_ + d);
        acc.x += hv * w.x; acc.y += hv * w.y;
        acc.z += hv * w.z; acc.w += hv * w.w;
    }
    if (mat == 0) { acc.x *= 0.25f; acc.y *= 0.25f; acc.z *= 0.25f; acc.w *= 0.25f; }
    *(float4*)(out + (size_t)row * C_ + d) = acc;
}

// ============================================================================
// Kernel 2 (the big one): Pe = e @ We fused with edge gating, e_out store,
// per-head channel reduction, clamp, transposed s store.
//
// Persistent CTAs. CTA = 256 threads (8 warps), 2 CTAs/SM (96 KB smem).
// Each chunk = 64 consecutive rows sharing (b,i); warp handles 8 rows (8 j's).
// Inner product uses packed fma.rn.f32x2; thread owns channels d=4*lane..+3.
// e tile staged TRANSPOSED ([c][r], 8 rows) with a conflict-free STS mapping.
// ============================================================================
__global__ void __launch_bounds__(256, 2)
edge_kernel(const float* __restrict__ e,
            const float* __restrict__ We,
            float* __restrict__ out_e) {
    extern __shared__ float smem[];
    float* sW = smem;                                   // 128*128 = 64 KB
    const int tid  = threadIdx.x;
    const int warp = tid >> 5;
    const int lane = tid & 31;
    float* sE = smem + C_ * C_ + warp * (C_ * 8);       // per-warp [c][r] tile

    // load We once per CTA
    for (int idx = tid; idx < C_ * C_ / 4; idx += 256)
        ((float4*)sW)[idx] = ((const float4*)We)[idx];
    __syncthreads();

    const int NCHUNK = B_ * N_ * N_ / 64;               // 8192
    const int r_mine = (lane >> 2) & 7;                 // row this lane stages
    const int c_off  = lane & 3;                        // c residue this lane stages

    for (int cid = blockIdx.x; cid < NCHUNK; cid += gridDim.x) {
        int bi = cid >> 3;                              // b*N + i
        int b  = bi >> 9;
        int i  = bi & (N_ - 1);
        int j0 = (cid & 7) << 6;
        int jw = j0 + warp * 8;

        // ---- stage 8 e rows transposed into sE[c*8 + r]  (conflict-free STS)
        {
            const float* erow = e + ((size_t)bi * N_ + jw + r_mine) * C_;
#pragma unroll 8
            for (int m = 0; m < 32; m++) {
                int c = 4 * m + c_off;
                sE[c * 8 + r_mine] = __ldg(erow + c);
            }
        }
        __syncwarp();

        // ---- main GEMM micro-kernel: acc[p][d] = f32x2 over rows (2p,2p+1)
        unsigned long long acc[4][4];
#pragma unroll
        for (int p = 0; p < 4; p++)
#pragma unroll
            for (int k = 0; k < 4; k++) acc[p][k] = 0ull;

        const float* sWl = sW + 4 * lane;
#pragma unroll 4
        for (int c = 0; c < C_; c++) {
            float4 w4 = *(const float4*)(sWl + c * C_);
            unsigned long long ws0 = pack2(w4.x, w4.x);
            unsigned long long ws1 = pack2(w4.y, w4.y);
            unsigned long long ws2 = pack2(w4.z, w4.z);
            unsigned long long ws3 = pack2(w4.w, w4.w);
            double2 ea = *(const double2*)(sE + c * 8);      // rows (0,1),(2,3)
            double2 eb = *(const double2*)(sE + c * 8 + 4);  // rows (4,5),(6,7)
            unsigned long long e01 = __double_as_longlong(ea.x);
            unsigned long long e23 = __double_as_longlong(ea.y);
            unsigned long long e45 = __double_as_longlong(eb.x);
            unsigned long long e67 = __double_as_longlong(eb.y);
            fma2(acc[0][0], e01, ws0); fma2(acc[0][1], e01, ws1);
            fma2(acc[0][2], e01, ws2); fma2(acc[0][3], e01, ws3);
            fma2(acc[1][0], e23, ws0); fma2(acc[1][1], e23, ws1);
            fma2(acc[1][2], e23, ws2); fma2(acc[1][3], e23, ws3);
            fma2(acc[2][0], e45, ws0); fma2(acc[2][1], e45, ws1);
            fma2(acc[2][2], e45, ws2); fma2(acc[2][3], e45, ws3);
            fma2(acc[3][0], e67, ws0); fma2(acc[3][1], e67, ws1);
            fma2(acc[3][2], e67, ws2); fma2(acc[3][3], e67, ws3);
        }
        __syncwarp();   // protect sE before next chunk overwrites it

        // ---- epilogue: gate by Q_i * K_j, store e_out, head-sum -> clamped s
        float4 q4 = *(const float4*)(g_Q + (size_t)bi * C_ + 4 * lane);
        int head = lane >> 2;
#pragma unroll
        for (int p = 0; p < 4; p++) {
            float2 a0 = unpack2(acc[p][0]);
            float2 a1 = unpack2(acc[p][1]);
            float2 a2 = unpack2(acc[p][2]);
            float2 a3 = unpack2(acc[p][3]);
#pragma unroll
            for (int sub = 0; sub < 2; sub++) {
                int j = jw + 2 * p + sub;
                float4 k4 = *(const float4*)(g_K + ((size_t)b * N_ + j) * C_ + 4 * lane);
                float4 eo;
                eo.x = (sub ? a0.y : a0.x) * q4.x * k4.x;
                eo.y = (sub ? a1.y : a1.x) * q4.y * k4.y;
                eo.z = (sub ? a2.y : a2.x) * q4.z * k4.z;
                eo.w = (sub ? a3.y : a3.x) * q4.w * k4.w;
                *(float4*)(out_e + ((size_t)bi * N_ + j) * C_ + 4 * lane) = eo;

                float hs = eo.x + eo.y + eo.z + eo.w;
                hs += __shfl_xor_sync(0xffffffffu, hs, 1);
                hs += __shfl_xor_sync(0xffffffffu, hs, 2);
                if ((lane & 3) == 0) {
                    hs = fminf(fmaxf(hs, -5.f), 5.f);
                    g_S[((size_t)(b * H_ + head) * N_ + j) * N_ + i] = hs;
                }
            }
        }
    }
}

// ============================================================================
// Kernel 3: softmax over the QUERY axis i.  g_S rows are [b,h,j][i] contiguous.
// One block per (b,h,j) row of 512 elements. Values pre-clamped to [-5,5], so
// no max-subtraction needed.
// ============================================================================
__global__ void softmax_kernel() {
    float* row = g_S + (size_t)blockIdx.x * N_;
    int tid = threadIdx.x;                       // 128 threads, 4 elems each
    float4 v = ((float4*)row)[tid];
    v.x = __expf(v.x); v.y = __expf(v.y); v.z = __expf(v.z); v.w = __expf(v.w);
    float s = v.x + v.y + v.z + v.w;
#pragma unroll
    for (int o = 16; o; o >>= 1) s += __shfl_xor_sync(0xffffffffu, s, o);
    __shared__ float ws[4];
    if ((tid & 31) == 0) ws[tid >> 5] = s;
    __syncthreads();
    float inv = 1.f / (ws[0] + ws[1] + ws[2] + ws[3]);
    v.x *= inv; v.y *= inv; v.z *= inv; v.w *= inv;
    ((float4*)row)[tid] = v;
}

// ============================================================================
// Kernel 4: h_out[b,i,h*16+c] = sum_j attn_T[b,h,j,i] * V[b,j,h*16+c]
// CTA = (b,h,i-tile of 64). 256 threads: lane-contiguous i for coalesced attn.
// ============================================================================
__global__ void hout_kernel(float* __restrict__ out_h) {
    int cta  = blockIdx.x;                       // 128 = 16 (b,h) * 8 i-tiles
    int bh   = cta >> 3;
    int b    = bh >> 3;
    int head = bh & 7;
    int i0   = (cta & 7) << 6;
    int t    = threadIdx.x;
    int ii   = t & 63;
    int cg   = t >> 6;                           // 0..3 -> channels cg*4..+3

    const float* arow = g_S + (size_t)bh * N_ * N_;
    const float* vcol = g_V + (size_t)b * N_ * C_ + head * CD_ + cg * 4;
    int i = i0 + ii;

    float4 acc = make_float4(0.f, 0.f, 0.f, 0.f);
#pragma unroll 4
    for (int j = 0; j < N_; j++) {
        float  a  = __ldg(arow + (size_t)j * N_ + i);
        float4 v4 = *(const float4*)(vcol + (size_t)j * C_);
        acc.x += a * v4.x; acc.y += a * v4.y;
        acc.z += a * v4.z; acc.w += a * v4.w;
    }
    *(float4*)(out_h + ((size_t)(b * N_ + i)) * C_ + head * CD_ + cg * 4) = acc;
}

// ============================================================================
extern "C" void kernel_launch(void* const* d_in, const int* in_sizes, int n_in,
                              void* d_out, int out_size) {
    const float* h  = (const float*)d_in[0];
    const float* e  = (const float*)d_in[1];
    const float* Wq = (const float*)d_in[2];
    const float* Wk = (const float*)d_in[3];
    const float* Wv = (const float*)d_in[4];
    const float* We = (const float*)d_in[5];

    float* out_h = (float*)d_out;                       // [B,N,C]
    float* out_e = (float*)d_out + B_ * N_ * C_;        // [B,N,N,C]

    // 96 KB dynamic smem for the edge kernel (idempotent; safe under capture)
    cudaFuncSetAttribute(edge_kernel,
                         cudaFuncAttributeMaxDynamicSharedMemorySize, 96 * 1024);

    qkv_kernel<<<384, 256>>>(h, Wq, Wk, Wv);
    edge_kernel<<<304, 256, 96 * 1024>>>(e, We, out_e);
    softmax_kernel<<<B_ * H_ * N_, 128>>>();
    hout_kernel<<<128, 256>>>(out_h);
}

// round 4
// speedup vs baseline: 1.0082x; 1.0082x over previous
#include <cuda_runtime.h>
#include <cstdint>

#define B_  2
#define N_  512
#define C_  128
#define H_  8
#define CD_ 16

// ---------------- scratch (device globals: no allocations allowed) ----------
__device__ float g_Q[B_ * N_ * C_];              // pre-scaled by 1/sqrt(CD)=0.25
__device__ float g_K[B_ * N_ * C_];
__device__ float g_V[B_ * N_ * C_];
__device__ float g_S[B_ * H_ * N_ * N_];         // stored TRANSPOSED: [b,h,j,i]

// ---------------- packed f32x2 helpers --------------------------------------
__device__ __forceinline__ void fma2(unsigned long long& acc,
                                     unsigned long long a,
                                     unsigned long long b) {
    asm("fma.rn.f32x2 %0, %1, %2, %0;" : "+l"(acc) : "l"(a), "l"(b));
}
__device__ __forceinline__ unsigned long long pack2(float lo, float hi) {
    unsigned long long r;
    asm("mov.b64 %0, {%1, %2};" : "=l"(r) : "f"(lo), "f"(hi));
    return r;
}
__device__ __forceinline__ float2 unpack2(unsigned long long v) {
    float2 f;
    asm("mov.b64 {%0, %1}, %2;" : "=f"(f.x), "=f"(f.y) : "l"(v));
    return f;
}

// ============================================================================
// Kernel 1: Q/K/V projections.  Q gets the 1/sqrt(CD) factor folded in.
// 98304 threads, each produces 4 outputs of one of {Q,K,V}.
// ============================================================================
__global__ void qkv_kernel(const float* __restrict__ h,
                           const float* __restrict__ Wq,
                           const float* __restrict__ Wk,
                           const float* __restrict__ Wv) {
    int gid = blockIdx.x * blockDim.x + threadIdx.x;   // [0, 98304)
    int row = gid / 96;                                // b*N + n
    int q   = gid % 96;
    int mat = q >> 5;                                  // 0:Q 1:K 2:V
    int d   = (q & 31) * 4;

    const float* W   = (mat == 0) ? Wq : (mat == 1) ? Wk : Wv;
    float*       out = (mat == 0) ? g_Q : (mat == 1) ? g_K : g_V;
    const float* hrow = h + (size_t)row * C_;

    float4 acc = make_float4(0.f, 0.f, 0.f, 0.f);
#pragma unroll 4
    for (int c = 0; c < C_; c++) {
        float  hv = __ldg(hrow + c);
        float4 w  = *(const float4*)(W + (size_t)c * C_ + d);
        acc.x += hv * w.x; acc.y += hv * w.y;
        acc.z += hv * w.z; acc.w += hv * w.w;
    }
    if (mat == 0) { acc.x *= 0.25f; acc.y *= 0.25f; acc.z *= 0.25f; acc.w *= 0.25f; }
    *(float4*)(out + (size_t)row * C_ + d) = acc;
}

// ============================================================================
// Kernel 2 (the big one): Pe = e @ We fused with edge gating, e_out store,
// per-head channel reduction, clamp, transposed s store.
//
// Persistent CTAs. CTA = 256 threads (8 warps), 2 CTAs/SM (96 KB smem).
// Each chunk = 64 consecutive rows sharing (b,i); warp handles 8 rows (8 j's).
// Inner product uses packed fma.rn.f32x2; thread owns channels d=4*lane..+3.
// e tile staged TRANSPOSED ([c][r], 8 rows) with a conflict-free STS mapping.
// ============================================================================
__global__ void __launch_bounds__(256, 2)
edge_kernel(const float* __restrict__ e,
            const float* __restrict__ We,
            float* __restrict__ out_e) {
    extern __shared__ float smem[];
    float* sW = smem;                                   // 128*128 = 64 KB
    const int tid  = threadIdx.x;
    const int warp = tid >> 5;
    const int lane = tid & 31;
    float* sE = smem + C_ * C_ + warp * (C_ * 8);       // per-warp [c][r] tile

    // load We once per CTA
    for (int idx = tid; idx < C_ * C_ / 4; idx += 256)
        ((float4*)sW)[idx] = ((const float4*)We)[idx];
    __syncthreads();

    const int NCHUNK = B_ * N_ * N_ / 64;               // 8192
    const int r_mine = (lane >> 2) & 7;                 // row this lane stages
    const int c_off  = lane & 3;                        // c residue this lane stages

    for (int cid = blockIdx.x; cid < NCHUNK; cid += gridDim.x) {
        int bi = cid >> 3;                              // b*N + i
        int b  = bi >> 9;
        int i  = bi & (N_ - 1);
        int j0 = (cid & 7) << 6;
        int jw = j0 + warp * 8;

        // ---- stage 8 e rows transposed into sE[c*8 + r]  (conflict-free STS)
        {
            const float* erow = e + ((size_t)bi * N_ + jw + r_mine) * C_;
#pragma unroll 8
            for (int m = 0; m < 32; m++) {
                int c = 4 * m + c_off;
                sE[c * 8 + r_mine] = __ldg(erow + c);
            }
        }
        __syncwarp();

        // ---- main GEMM micro-kernel: acc[p][d] = f32x2 over rows (2p,2p+1)
        unsigned long long acc[4][4];
#pragma unroll
        for (int p = 0; p < 4; p++)
#pragma unroll
            for (int k = 0; k < 4; k++) acc[p][k] = 0ull;

        const float* sWl = sW + 4 * lane;
#pragma unroll 4
        for (int c = 0; c < C_; c++) {
            float4 w4 = *(const float4*)(sWl + c * C_);
            unsigned long long ws0 = pack2(w4.x, w4.x);
            unsigned long long ws1 = pack2(w4.y, w4.y);
            unsigned long long ws2 = pack2(w4.z, w4.z);
            unsigned long long ws3 = pack2(w4.w, w4.w);
            double2 ea = *(const double2*)(sE + c * 8);      // rows (0,1),(2,3)
            double2 eb = *(const double2*)(sE + c * 8 + 4);  // rows (4,5),(6,7)
            unsigned long long e01 = __double_as_longlong(ea.x);
            unsigned long long e23 = __double_as_longlong(ea.y);
            unsigned long long e45 = __double_as_longlong(eb.x);
            unsigned long long e67 = __double_as_longlong(eb.y);
            fma2(acc[0][0], e01, ws0); fma2(acc[0][1], e01, ws1);
            fma2(acc[0][2], e01, ws2); fma2(acc[0][3], e01, ws3);
            fma2(acc[1][0], e23, ws0); fma2(acc[1][1], e23, ws1);
            fma2(acc[1][2], e23, ws2); fma2(acc[1][3], e23, ws3);
            fma2(acc[2][0], e45, ws0); fma2(acc[2][1], e45, ws1);
            fma2(acc[2][2], e45, ws2); fma2(acc[2][3], e45, ws3);
            fma2(acc[3][0], e67, ws0); fma2(acc[3][1], e67, ws1);
            fma2(acc[3][2], e67, ws2); fma2(acc[3][3], e67, ws3);
        }
        __syncwarp();   // protect sE before next chunk overwrites it

        // ---- epilogue: gate by Q_i * K_j, store e_out, head-sum -> clamped s
        float4 q4 = *(const float4*)(g_Q + (size_t)bi * C_ + 4 * lane);
        int head = lane >> 2;
#pragma unroll
        for (int p = 0; p < 4; p++) {
            float2 a0 = unpack2(acc[p][0]);
            float2 a1 = unpack2(acc[p][1]);
            float2 a2 = unpack2(acc[p][2]);
            float2 a3 = unpack2(acc[p][3]);
#pragma unroll
            for (int sub = 0; sub < 2; sub++) {
                int j = jw + 2 * p + sub;
                float4 k4 = *(const float4*)(g_K + ((size_t)b * N_ + j) * C_ + 4 * lane);
                float4 eo;
                eo.x = (sub ? a0.y : a0.x) * q4.x * k4.x;
                eo.y = (sub ? a1.y : a1.x) * q4.y * k4.y;
                eo.z = (sub ? a2.y : a2.x) * q4.z * k4.z;
                eo.w = (sub ? a3.y : a3.x) * q4.w * k4.w;
                *(float4*)(out_e + ((size_t)bi * N_ + j) * C_ + 4 * lane) = eo;

                float hs = eo.x + eo.y + eo.z + eo.w;
                hs += __shfl_xor_sync(0xffffffffu, hs, 1);
                hs += __shfl_xor_sync(0xffffffffu, hs, 2);
                if ((lane & 3) == 0) {
                    hs = fminf(fmaxf(hs, -5.f), 5.f);
                    g_S[((size_t)(b * H_ + head) * N_ + j) * N_ + i] = hs;
                }
            }
        }
    }
}

// ============================================================================
// Kernel 3: softmax over the QUERY axis i.  g_S rows are [b,h,j][i] contiguous.
// One block per (b,h,j) row of 512 elements. Values pre-clamped to [-5,5], so
// no max-subtraction needed.
// ============================================================================
__global__ void softmax_kernel() {
    float* row = g_S + (size_t)blockIdx.x * N_;
    int tid = threadIdx.x;                       // 128 threads, 4 elems each
    float4 v = ((float4*)row)[tid];
    v.x = __expf(v.x); v.y = __expf(v.y); v.z = __expf(v.z); v.w = __expf(v.w);
    float s = v.x + v.y + v.z + v.w;
#pragma unroll
    for (int o = 16; o; o >>= 1) s += __shfl_xor_sync(0xffffffffu, s, o);
    __shared__ float ws[4];
    if ((tid & 31) == 0) ws[tid >> 5] = s;
    __syncthreads();
    float inv = 1.f / (ws[0] + ws[1] + ws[2] + ws[3]);
    v.x *= inv; v.y *= inv; v.z *= inv; v.w *= inv;
    ((float4*)row)[tid] = v;
}

// ============================================================================
// Kernel 4: h_out[b,i,h*16+c] = sum_j attn_T[b,h,j,i] * V[b,j,h*16+c]
// CTA = (b,h,i-tile of 64). 256 threads: lane-contiguous i for coalesced attn.
// ============================================================================
__global__ void hout_kernel(float* __restrict__ out_h) {
    int cta  = blockIdx.x;                       // 128 = 16 (b,h) * 8 i-tiles
    int bh   = cta >> 3;
    int b    = bh >> 3;
    int head = bh & 7;
    int i0   = (cta & 7) << 6;
    int t    = threadIdx.x;
    int ii   = t & 63;
    int cg   = t >> 6;                           // 0..3 -> channels cg*4..+3

    const float* arow = g_S + (size_t)bh * N_ * N_;
    const float* vcol = g_V + (size_t)b * N_ * C_ + head * CD_ + cg * 4;
    int i = i0 + ii;

    float4 acc = make_float4(0.f, 0.f, 0.f, 0.f);
#pragma unroll 4
    for (int j = 0; j < N_; j++) {
        float  a  = __ldg(arow + (size_t)j * N_ + i);
        float4 v4 = *(const float4*)(vcol + (size_t)j * C_);
        acc.x += a * v4.x; acc.y += a * v4.y;
        acc.z += a * v4.z; acc.w += a * v4.w;
    }
    *(float4*)(out_h + ((size_t)(b * N_ + i)) * C_ + head * CD_ + cg * 4) = acc;
}

// ============================================================================
extern "C" void kernel_launch(void* const* d_in, const int* in_sizes, int n_in,
                              void* d_out, int out_size) {
    const float* h  = (const float*)d_in[0];
    const float* e  = (const float*)d_in[1];
    const float* Wq = (const float*)d_in[2];
    const float* Wk = (const float*)d_in[3];
    const float* Wv = (const float*)d_in[4];
    const float* We = (const float*)d_in[5];

    float* out_h = (float*)d_out;                       // [B,N,C]
    float* out_e = (float*)d_out + B_ * N_ * C_;        // [B,N,N,C]

    // 96 KB dynamic smem for the edge kernel (idempotent; safe under capture)
    cudaFuncSetAttribute(edge_kernel,
                         cudaFuncAttributeMaxDynamicSharedMemorySize, 96 * 1024);

    qkv_kernel<<<384, 256>>>(h, Wq, Wk, Wv);
    edge_kernel<<<304, 256, 96 * 1024>>>(e, We, out_e);
    softmax_kernel<<<B_ * H_ * N_, 128>>>();
    hout_kernel<<<128, 256>>>(out_h);
}

// round 5
// speedup vs baseline: 1.0100x; 1.0018x over previous
#include <cuda_runtime.h>
#include <cstdint>

#define B_  2
#define N_  512
#define C_  128
#define H_  8
#define CD_ 16

// ---------------- scratch (device globals: no allocations allowed) ----------
__device__ float g_Q[B_ * N_ * C_];              // pre-scaled by 1/sqrt(CD)=0.25
__device__ float g_K[B_ * N_ * C_];
__device__ float g_V[B_ * N_ * C_];
__device__ float g_S[B_ * H_ * N_ * N_];         // stored TRANSPOSED: [b,h,j,i]

// ---------------- packed f32x2 helpers --------------------------------------
__device__ __forceinline__ void fma2(unsigned long long& acc,
                                     unsigned long long a,
                                     unsigned long long b) {
    asm("fma.rn.f32x2 %0, %1, %2, %0;" : "+l"(acc) : "l"(a), "l"(b));
}
__device__ __forceinline__ unsigned long long pack2(float lo, float hi) {
    unsigned long long r;
    asm("mov.b64 %0, {%1, %2};" : "=l"(r) : "f"(lo), "f"(hi));
    return r;
}
__device__ __forceinline__ float2 unpack2(unsigned long long v) {
    float2 f;
    asm("mov.b64 {%0, %1}, %2;" : "=f"(f.x), "=f"(f.y) : "l"(v));
    return f;
}

// ============================================================================
// Kernel 1: Q/K/V projections.  Q gets the 1/sqrt(CD) factor folded in.
// 98304 threads, each produces 4 outputs of one of {Q,K,V}.
// ============================================================================
__global__ void qkv_kernel(const float* __restrict__ h,
                           const float* __restrict__ Wq,
                           const float* __restrict__ Wk,
                           const float* __restrict__ Wv) {
    int gid = blockIdx.x * blockDim.x + threadIdx.x;   // [0, 98304)
    int row = gid / 96;                                // b*N + n
    int q   = gid % 96;
    int mat = q >> 5;                                  // 0:Q 1:K 2:V
    int d   = (q & 31) * 4;

    const float* W   = (mat == 0) ? Wq : (mat == 1) ? Wk : Wv;
    float*       out = (mat == 0) ? g_Q : (mat == 1) ? g_K : g_V;
    const float* hrow = h + (size_t)row * C_;

    float4 acc = make_float4(0.f, 0.f, 0.f, 0.f);
#pragma unroll 4
    for (int c = 0; c < C_; c++) {
        float  hv = __ldg(hrow + c);
        float4 w  = *(const float4*)(W + (size_t)c * C_ + d);
        acc.x += hv * w.x; acc.y += hv * w.y;
        acc.z += hv * w.z; acc.w += hv * w.w;
    }
    if (mat == 0) { acc.x *= 0.25f; acc.y *= 0.25f; acc.z *= 0.25f; acc.w *= 0.25f; }
    *(float4*)(out + (size_t)row * C_ + d) = acc;
}

// ============================================================================
// Kernel 2 (the big one): Pe = e @ We fused with edge gating, e_out store,
// per-head channel reduction, clamp, transposed s store.
//
// Persistent CTAs. CTA = 256 threads (8 warps), 2 CTAs/SM (96 KB smem).
// Each chunk = 64 consecutive rows sharing (b,i); warp handles 8 rows (8 j's).
// Inner product uses packed fma.rn.f32x2; thread owns channels d=4*lane..+3.
// e tile staged TRANSPOSED ([c][r], 8 rows) with a conflict-free STS mapping.
// ============================================================================
__global__ void __launch_bounds__(256, 2)
edge_kernel(const float* __restrict__ e,
            const float* __restrict__ We,
            float* __restrict__ out_e) {
    extern __shared__ float smem[];
    float* sW = smem;                                   // 128*128 = 64 KB
    const int tid  = threadIdx.x;
    const int warp = tid >> 5;
    const int lane = tid & 31;
    float* sE = smem + C_ * C_ + warp * (C_ * 8);       // per-warp [c][r] tile

    // load We once per CTA
    for (int idx = tid; idx < C_ * C_ / 4; idx += 256)
        ((float4*)sW)[idx] = ((const float4*)We)[idx];
    __syncthreads();

    const int NCHUNK = B_ * N_ * N_ / 64;               // 8192
    const int r_mine = (lane >> 2) & 7;                 // row this lane stages
    const int c_off  = lane & 3;                        // c residue this lane stages

    for (int cid = blockIdx.x; cid < NCHUNK; cid += gridDim.x) {
        int bi = cid >> 3;                              // b*N + i
        int b  = bi >> 9;
        int i  = bi & (N_ - 1);
        int j0 = (cid & 7) << 6;
        int jw = j0 + warp * 8;

        // ---- stage 8 e rows transposed into sE[c*8 + r]  (conflict-free STS)
        {
            const float* erow = e + ((size_t)bi * N_ + jw + r_mine) * C_;
#pragma unroll 8
            for (int m = 0; m < 32; m++) {
                int c = 4 * m + c_off;
                sE[c * 8 + r_mine] = __ldg(erow + c);
            }
        }
        __syncwarp();

        // ---- main GEMM micro-kernel: acc[p][d] = f32x2 over rows (2p,2p+1)
        unsigned long long acc[4][4];
#pragma unroll
        for (int p = 0; p < 4; p++)
#pragma unroll
            for (int k = 0; k < 4; k++) acc[p][k] = 0ull;

        const float* sWl = sW + 4 * lane;
#pragma unroll 4
        for (int c = 0; c < C_; c++) {
            float4 w4 = *(const float4*)(sWl + c * C_);
            unsigned long long ws0 = pack2(w4.x, w4.x);
            unsigned long long ws1 = pack2(w4.y, w4.y);
            unsigned long long ws2 = pack2(w4.z, w4.z);
            unsigned long long ws3 = pack2(w4.w, w4.w);
            double2 ea = *(const double2*)(sE + c * 8);      // rows (0,1),(2,3)
            double2 eb = *(const double2*)(sE + c * 8 + 4);  // rows (4,5),(6,7)
            unsigned long long e01 = __double_as_longlong(ea.x);
            unsigned long long e23 = __double_as_longlong(ea.y);
            unsigned long long e45 = __double_as_longlong(eb.x);
            unsigned long long e67 = __double_as_longlong(eb.y);
            fma2(acc[0][0], e01, ws0); fma2(acc[0][1], e01, ws1);
            fma2(acc[0][2], e01, ws2); fma2(acc[0][3], e01, ws3);
            fma2(acc[1][0], e23, ws0); fma2(acc[1][1], e23, ws1);
            fma2(acc[1][2], e23, ws2); fma2(acc[1][3], e23, ws3);
            fma2(acc[2][0], e45, ws0); fma2(acc[2][1], e45, ws1);
            fma2(acc[2][2], e45, ws2); fma2(acc[2][3], e45, ws3);
            fma2(acc[3][0], e67, ws0); fma2(acc[3][1], e67, ws1);
            fma2(acc[3][2], e67, ws2); fma2(acc[3][3], e67, ws3);
        }
        __syncwarp();   // protect sE before next chunk overwrites it

        // ---- epilogue: gate by Q_i * K_j, store e_out, head-sum -> clamped s
        float4 q4 = *(const float4*)(g_Q + (size_t)bi * C_ + 4 * lane);
        int head = lane >> 2;
#pragma unroll
        for (int p = 0; p < 4; p++) {
            float2 a0 = unpack2(acc[p][0]);
            float2 a1 = unpack2(acc[p][1]);
            float2 a2 = unpack2(acc[p][2]);
            float2 a3 = unpack2(acc[p][3]);
#pragma unroll
            for (int sub = 0; sub < 2; sub++) {
                int j = jw + 2 * p + sub;
                float4 k4 = *(const float4*)(g_K + ((size_t)b * N_ + j) * C_ + 4 * lane);
                float4 eo;
                eo.x = (sub ? a0.y : a0.x) * q4.x * k4.x;
                eo.y = (sub ? a1.y : a1.x) * q4.y * k4.y;
                eo.z = (sub ? a2.y : a2.x) * q4.z * k4.z;
                eo.w = (sub ? a3.y : a3.x) * q4.w * k4.w;
                *(float4*)(out_e + ((size_t)bi * N_ + j) * C_ + 4 * lane) = eo;

                float hs = eo.x + eo.y + eo.z + eo.w;
                hs += __shfl_xor_sync(0xffffffffu, hs, 1);
                hs += __shfl_xor_sync(0xffffffffu, hs, 2);
                if ((lane & 3) == 0) {
                    hs = fminf(fmaxf(hs, -5.f), 5.f);
                    g_S[((size_t)(b * H_ + head) * N_ + j) * N_ + i] = hs;
                }
            }
        }
    }
}

// ============================================================================
// Kernel 3: softmax over the QUERY axis i.  g_S rows are [b,h,j][i] contiguous.
// One block per (b,h,j) row of 512 elements. Values pre-clamped to [-5,5], so
// no max-subtraction needed.
// ============================================================================
__global__ void softmax_kernel() {
    float* row = g_S + (size_t)blockIdx.x * N_;
    int tid = threadIdx.x;                       // 128 threads, 4 elems each
    float4 v = ((float4*)row)[tid];
    v.x = __expf(v.x); v.y = __expf(v.y); v.z = __expf(v.z); v.w = __expf(v.w);
    float s = v.x + v.y + v.z + v.w;
#pragma unroll
    for (int o = 16; o; o >>= 1) s += __shfl_xor_sync(0xffffffffu, s, o);
    __shared__ float ws[4];
    if ((tid & 31) == 0) ws[tid >> 5] = s;
    __syncthreads();
    float inv = 1.f / (ws[0] + ws[1] + ws[2] + ws[3]);
    v.x *= inv; v.y *= inv; v.z *= inv; v.w *= inv;
    ((float4*)row)[tid] = v;
}

// ============================================================================
// Kernel 4: h_out[b,i,h*16+c] = sum_j attn_T[b,h,j,i] * V[b,j,h*16+c]
// CTA = (b,h,i-tile of 64). 256 threads: lane-contiguous i for coalesced attn.
// ============================================================================
__global__ void hout_kernel(float* __restrict__ out_h) {
    int cta  = blockIdx.x;                       // 128 = 16 (b,h) * 8 i-tiles
    int bh   = cta >> 3;
    int b    = bh >> 3;
    int head = bh & 7;
    int i0   = (cta & 7) << 6;
    int t    = threadIdx.x;
    int ii   = t & 63;
    int cg   = t >> 6;                           // 0..3 -> channels cg*4..+3

    const float* arow = g_S + (size_t)bh * N_ * N_;
    const float* vcol = g_V + (size_t)b * N_ * C_ + head * CD_ + cg * 4;
    int i = i0 + ii;

    float4 acc = make_float4(0.f, 0.f, 0.f, 0.f);
#pragma unroll 4
    for (int j = 0; j < N_; j++) {
        float  a  = __ldg(arow + (size_t)j * N_ + i);
        float4 v4 = *(const float4*)(vcol + (size_t)j * C_);
        acc.x += a * v4.x; acc.y += a * v4.y;
        acc.z += a * v4.z; acc.w += a * v4.w;
    }
    *(float4*)(out_h + ((size_t)(b * N_ + i)) * C_ + head * CD_ + cg * 4) = acc;
}

// ============================================================================
extern "C" void kernel_launch(void* const* d_in, const int* in_sizes, int n_in,
                              void* d_out, int out_size) {
    const float* h  = (const float*)d_in[0];
    const float* e  = (const float*)d_in[1];
    const float* Wq = (const float*)d_in[2];
    const float* Wk = (const float*)d_in[3];
    const float* Wv = (const float*)d_in[4];
    const float* We = (const float*)d_in[5];

    float* out_h = (float*)d_out;                       // [B,N,C]
    float* out_e = (float*)d_out + B_ * N_ * C_;        // [B,N,N,C]

    // 96 KB dynamic smem for the edge kernel (idempotent; safe under capture)
    cudaFuncSetAttribute(edge_kernel,
                         cudaFuncAttributeMaxDynamicSharedMemorySize, 96 * 1024);

    qkv_kernel<<<384, 256>>>(h, Wq, Wk, Wv);
    edge_kernel<<<304, 256, 96 * 1024>>>(e, We, out_e);
    softmax_kernel<<<B_ * H_ * N_, 128>>>();
    hout_kernel<<<128, 256>>>(out_h);
}

// round 6
// speedup vs baseline: 1.0103x; 1.0004x over previous
#include <cuda_runtime.h>
#include <cstdint>

#define B_  2
#define N_  512
#define C_  128
#define H_  8
#define CD_ 16

// ---------------- scratch (device globals: no allocations allowed) ----------
__device__ float g_Q[B_ * N_ * C_];              // pre-scaled by 1/sqrt(CD)=0.25
__device__ float g_K[B_ * N_ * C_];
__device__ float g_V[B_ * N_ * C_];
__device__ float g_S[B_ * H_ * N_ * N_];         // stored TRANSPOSED: [b,h,j,i]

// ---------------- packed f32x2 helpers --------------------------------------
__device__ __forceinline__ void fma2(unsigned long long& acc,
                                     unsigned long long a,
                                     unsigned long long b) {
    asm("fma.rn.f32x2 %0, %1, %2, %0;" : "+l"(acc) : "l"(a), "l"(b));
}
__device__ __forceinline__ unsigned long long pack2(float lo, float hi) {
    unsigned long long r;
    asm("mov.b64 %0, {%1, %2};" : "=l"(r) : "f"(lo), "f"(hi));
    return r;
}
__device__ __forceinline__ float2 unpack2(unsigned long long v) {
    float2 f;
    asm("mov.b64 {%0, %1}, %2;" : "=f"(f.x), "=f"(f.y) : "l"(v));
    return f;
}

// ============================================================================
// Kernel 1: Q/K/V projections.  Q gets the 1/sqrt(CD) factor folded in.
// 98304 threads, each produces 4 outputs of one of {Q,K,V}.
// ============================================================================
__global__ void qkv_kernel(const float* __restrict__ h,
                           const float* __restrict__ Wq,
                           const float* __restrict__ Wk,
                           const float* __restrict__ Wv) {
    int gid = blockIdx.x * blockDim.x + threadIdx.x;   // [0, 98304)
    int row = gid / 96;                                // b*N + n
    int q   = gid % 96;
    int mat = q >> 5;                                  // 0:Q 1:K 2:V
    int d   = (q & 31) * 4;

    const float* W   = (mat == 0) ? Wq : (mat == 1) ? Wk : Wv;
    float*       out = (mat == 0) ? g_Q : (mat == 1) ? g_K : g_V;
    const float* hrow = h + (size_t)row * C_;

    float4 acc = make_float4(0.f, 0.f, 0.f, 0.f);
#pragma unroll 4
    for (int c = 0; c < C_; c++) {
        float  hv = __ldg(hrow + c);
        float4 w  = *(const float4*)(W + (size_t)c * C_ + d);
        acc.x += hv * w.x; acc.y += hv * w.y;
        acc.z += hv * w.z; acc.w += hv * w.w;
    }
    if (mat == 0) { acc.x *= 0.25f; acc.y *= 0.25f; acc.z *= 0.25f; acc.w *= 0.25f; }
    *(float4*)(out + (size_t)row * C_ + d) = acc;
}

// ============================================================================
// Kernel 2 (the big one): Pe = e @ We fused with edge gating, e_out store,
// per-head channel reduction, clamp, transposed s store.
//
// Persistent CTAs. CTA = 256 threads (8 warps), 2 CTAs/SM (96 KB smem).
// Each chunk = 64 consecutive rows sharing (b,i); warp handles 8 rows (8 j's).
// Inner product uses packed fma.rn.f32x2; thread owns channels d=4*lane..+3.
// e tile staged TRANSPOSED ([c][r], 8 rows) with a conflict-free STS mapping.
// ============================================================================
__global__ void __launch_bounds__(256, 2)
edge_kernel(const float* __restrict__ e,
            const float* __restrict__ We,
            float* __restrict__ out_e) {
    extern __shared__ float smem[];
    float* sW = smem;                                   // 128*128 = 64 KB
    const int tid  = threadIdx.x;
    const int warp = tid >> 5;
    const int lane = tid & 31;
    float* sE = smem + C_ * C_ + warp * (C_ * 8);       // per-warp [c][r] tile

    // load We once per CTA
    for (int idx = tid; idx < C_ * C_ / 4; idx += 256)
        ((float4*)sW)[idx] = ((const float4*)We)[idx];
    __syncthreads();

    const int NCHUNK = B_ * N_ * N_ / 64;               // 8192
    const int r_mine = (lane >> 2) & 7;                 // row this lane stages
    const int c_off  = lane & 3;                        // c residue this lane stages

    for (int cid = blockIdx.x; cid < NCHUNK; cid += gridDim.x) {
        int bi = cid >> 3;                              // b*N + i
        int b  = bi >> 9;
        int i  = bi & (N_ - 1);
        int j0 = (cid & 7) << 6;
        int jw = j0 + warp * 8;

        // ---- stage 8 e rows transposed into sE[c*8 + r]  (conflict-free STS)
        {
            const float* erow = e + ((size_t)bi * N_ + jw + r_mine) * C_;
#pragma unroll 8
            for (int m = 0; m < 32; m++) {
                int c = 4 * m + c_off;
                sE[c * 8 + r_mine] = __ldg(erow + c);
            }
        }
        __syncwarp();

        // ---- main GEMM micro-kernel: acc[p][d] = f32x2 over rows (2p,2p+1)
        unsigned long long acc[4][4];
#pragma unroll
        for (int p = 0; p < 4; p++)
#pragma unroll
            for (int k = 0; k < 4; k++) acc[p][k] = 0ull;

        const float* sWl = sW + 4 * lane;
#pragma unroll 4
        for (int c = 0; c < C_; c++) {
            float4 w4 = *(const float4*)(sWl + c * C_);
            unsigned long long ws0 = pack2(w4.x, w4.x);
            unsigned long long ws1 = pack2(w4.y, w4.y);
            unsigned long long ws2 = pack2(w4.z, w4.z);
            unsigned long long ws3 = pack2(w4.w, w4.w);
            double2 ea = *(const double2*)(sE + c * 8);      // rows (0,1),(2,3)
            double2 eb = *(const double2*)(sE + c * 8 + 4);  // rows (4,5),(6,7)
            unsigned long long e01 = __double_as_longlong(ea.x);
            unsigned long long e23 = __double_as_longlong(ea.y);
            unsigned long long e45 = __double_as_longlong(eb.x);
            unsigned long long e67 = __double_as_longlong(eb.y);
            fma2(acc[0][0], e01, ws0); fma2(acc[0][1], e01, ws1);
            fma2(acc[0][2], e01, ws2); fma2(acc[0][3], e01, ws3);
            fma2(acc[1][0], e23, ws0); fma2(acc[1][1], e23, ws1);
            fma2(acc[1][2], e23, ws2); fma2(acc[1][3], e23, ws3);
            fma2(acc[2][0], e45, ws0); fma2(acc[2][1], e45, ws1);
            fma2(acc[2][2], e45, ws2); fma2(acc[2][3], e45, ws3);
            fma2(acc[3][0], e67, ws0); fma2(acc[3][1], e67, ws1);
            fma2(acc[3][2], e67, ws2); fma2(acc[3][3], e67, ws3);
        }
        __syncwarp();   // protect sE before next chunk overwrites it

        // ---- epilogue: gate by Q_i * K_j, store e_out, head-sum -> clamped s
        float4 q4 = *(const float4*)(g_Q + (size_t)bi * C_ + 4 * lane);
        int head = lane >> 2;
#pragma unroll
        for (int p = 0; p < 4; p++) {
            float2 a0 = unpack2(acc[p][0]);
            float2 a1 = unpack2(acc[p][1]);
            float2 a2 = unpack2(acc[p][2]);
            float2 a3 = unpack2(acc[p][3]);
#pragma unroll
            for (int sub = 0; sub < 2; sub++) {
                int j = jw + 2 * p + sub;
                float4 k4 = *(const float4*)(g_K + ((size_t)b * N_ + j) * C_ + 4 * lane);
                float4 eo;
                eo.x = (sub ? a0.y : a0.x) * q4.x * k4.x;
                eo.y = (sub ? a1.y : a1.x) * q4.y * k4.y;
                eo.z = (sub ? a2.y : a2.x) * q4.z * k4.z;
                eo.w = (sub ? a3.y : a3.x) * q4.w * k4.w;
                *(float4*)(out_e + ((size_t)bi * N_ + j) * C_ + 4 * lane) = eo;

                float hs = eo.x + eo.y + eo.z + eo.w;
                hs += __shfl_xor_sync(0xffffffffu, hs, 1);
                hs += __shfl_xor_sync(0xffffffffu, hs, 2);
                if ((lane & 3) == 0) {
                    hs = fminf(fmaxf(hs, -5.f), 5.f);
                    g_S[((size_t)(b * H_ + head) * N_ + j) * N_ + i] = hs;
                }
            }
        }
    }
}

// ============================================================================
// Kernel 3: softmax over the QUERY axis i.  g_S rows are [b,h,j][i] contiguous.
// One block per (b,h,j) row of 512 elements. Values pre-clamped to [-5,5], so
// no max-subtraction needed.
// ============================================================================
__global__ void softmax_kernel() {
    float* row = g_S + (size_t)blockIdx.x * N_;
    int tid = threadIdx.x;                       // 128 threads, 4 elems each
    float4 v = ((float4*)row)[tid];
    v.x = __expf(v.x); v.y = __expf(v.y); v.z = __expf(v.z); v.w = __expf(v.w);
    float s = v.x + v.y + v.z + v.w;
#pragma unroll
    for (int o = 16; o; o >>= 1) s += __shfl_xor_sync(0xffffffffu, s, o);
    __shared__ float ws[4];
    if ((tid & 31) == 0) ws[tid >> 5] = s;
    __syncthreads();
    float inv = 1.f / (ws[0] + ws[1] + ws[2] + ws[3]);
    v.x *= inv; v.y *= inv; v.z *= inv; v.w *= inv;
    ((float4*)row)[tid] = v;
}

// ============================================================================
// Kernel 4: h_out[b,i,h*16+c] = sum_j attn_T[b,h,j,i] * V[b,j,h*16+c]
// CTA = (b,h,i-tile of 64). 256 threads: lane-contiguous i for coalesced attn.
// ============================================================================
__global__ void hout_kernel(float* __restrict__ out_h) {
    int cta  = blockIdx.x;                       // 128 = 16 (b,h) * 8 i-tiles
    int bh   = cta >> 3;
    int b    = bh >> 3;
    int head = bh & 7;
    int i0   = (cta & 7) << 6;
    int t    = threadIdx.x;
    int ii   = t & 63;
    int cg   = t >> 6;                           // 0..3 -> channels cg*4..+3

    const float* arow = g_S + (size_t)bh * N_ * N_;
    const float* vcol = g_V + (size_t)b * N_ * C_ + head * CD_ + cg * 4;
    int i = i0 + ii;

    float4 acc = make_float4(0.f, 0.f, 0.f, 0.f);
#pragma unroll 4
    for (int j = 0; j < N_; j++) {
        float  a  = __ldg(arow + (size_t)j * N_ + i);
        float4 v4 = *(const float4*)(vcol + (size_t)j * C_);
        acc.x += a * v4.x; acc.y += a * v4.y;
        acc.z += a * v4.z; acc.w += a * v4.w;
    }
    *(float4*)(out_h + ((size_t)(b * N_ + i)) * C_ + head * CD_ + cg * 4) = acc;
}

// ============================================================================
extern "C" void kernel_launch(void* const* d_in, const int* in_sizes, int n_in,
                              void* d_out, int out_size) {
    const float* h  = (const float*)d_in[0];
    const float* e  = (const float*)d_in[1];
    const float* Wq = (const float*)d_in[2];
    const float* Wk = (const float*)d_in[3];
    const float* Wv = (const float*)d_in[4];
    const float* We = (const float*)d_in[5];

    float* out_h = (float*)d_out;                       // [B,N,C]
    float* out_e = (float*)d_out + B_ * N_ * C_;        // [B,N,N,C]

    // 96 KB dynamic smem for the edge kernel (idempotent; safe under capture)
    cudaFuncSetAttribute(edge_kernel,
                         cudaFuncAttributeMaxDynamicSharedMemorySize, 96 * 1024);

    qkv_kernel<<<384, 256>>>(h, Wq, Wk, Wv);
    edge_kernel<<<304, 256, 96 * 1024>>>(e, We, out_e);
    softmax_kernel<<<B_ * H_ * N_, 128>>>();
    hout_kernel<<<128, 256>>>(out_h);
}

// round 8
// speedup vs baseline: 1.5879x; 1.5717x over previous
#include <cuda_runtime.h>
#include <cuda_bf16.h>
#include <cstdint>

#define B_  2
#define N_  512
#define C_  128
#define H_  8

// ---------------- scratch (device globals) ----------------------------------
__device__ float g_Q[B_ * N_ * C_];               // pre-scaled by 0.25
__device__ float g_K[B_ * N_ * C_];
__device__ float g_V[B_ * N_ * C_];
__device__ float g_S[B_ * H_ * N_ * N_];          // [b,h,i,j]; exp'ed in place
__device__ float g_cs[8 * 16 * N_];               // colsum partials [s8][bh][j]
__device__ __nv_bfloat16 g_W0T[C_ * C_];          // WeT hi split [d][c]
__device__ __nv_bfloat16 g_W1T[C_ * C_];          // WeT lo split [d][c]

// ---------------- helpers ----------------------------------------------------
__device__ __forceinline__ uint32_t smem_u32(const void* p) {
    uint32_t a;
    asm("{ .reg .u64 t; cvta.to.shared.u64 t, %1; cvt.u32.u64 %0, t; }" : "=r"(a) : "l"(p));
    return a;
}
#define LDSM_X4(r0, r1, r2, r3, a) \
    asm volatile("ldmatrix.sync.aligned.m8n8.x4.shared.b16 {%0,%1,%2,%3}, [%4];" \
                 : "=r"(r0), "=r"(r1), "=r"(r2), "=r"(r3) : "r"(a))
#define LDSM_X2(r0, r1, a) \
    asm volatile("ldmatrix.sync.aligned.m8n8.x2.shared.b16 {%0,%1}, [%2];" \
                 : "=r"(r0), "=r"(r1) : "r"(a))
#define MMA16816(c, a0, a1, a2, a3, b0, b1) \
    asm volatile("mma.sync.aligned.m16n8k16.row.col.f32.bf16.bf16.f32 " \
                 "{%0,%1,%2,%3}, {%4,%5,%6,%7}, {%8,%9}, {%0,%1,%2,%3};" \
                 : "+f"((c)[0]), "+f"((c)[1]), "+f"((c)[2]), "+f"((c)[3]) \
                 : "r"(a0), "r"(a1), "r"(a2), "r"(a3), "r"(b0), "r"(b1))
#define STS64(a, u0, u1) \
    asm volatile("st.shared.v2.u32 [%0], {%1, %2};" :: "r"(a), "r"(u0), "r"(u1) : "memory")

// XOR swizzle on 16B chunks within a 256B row (bits 4..6)
__device__ __forceinline__ uint32_t swz(int row, uint32_t cb) {
    return (uint32_t)row * 256u + (cb ^ (((uint32_t)row & 7u) << 4));
}

// dynamic smem byte offsets
#define SM_W0   0u
#define SM_W1   32768u
#define SM_E0   65536u
#define SM_E1   98304u
#define SM_KO   131072u            // 128 rows * 132 floats = 67584 B
#define SM_Q    198656u            // 128 floats
#define SM_TOT  199680u

// ============================================================================
// Kernel 0: transpose + bf16-split We -> g_W0T/g_W1T [d][c]
// ============================================================================
__global__ void prep_w_kernel(const float* __restrict__ We) {
    int idx = blockIdx.x * 256 + threadIdx.x;      // [0, 16384)
    int d = idx >> 7, c = idx & 127;
    float w = __ldg(We + c * C_ + d);
    __nv_bfloat16 hi = __float2bfloat16_rn(w);
    g_W0T[idx] = hi;
    g_W1T[idx] = __float2bfloat16_rn(w - __bfloat162float(hi));
}

// ============================================================================
// Kernel 1: Q/K/V projections (Q pre-scaled by 0.25)
// ============================================================================
__global__ void qkv_kernel(const float* __restrict__ h, const float* __restrict__ Wq,
                           const float* __restrict__ Wk, const float* __restrict__ Wv) {
    int gid = blockIdx.x * blockDim.x + threadIdx.x;   // [0, 98304)
    int row = gid / 96, q = gid % 96;
    int mat = q >> 5, d = (q & 31) * 4;
    const float* W   = (mat == 0) ? Wq : (mat == 1) ? Wk : Wv;
    float*       out = (mat == 0) ? g_Q : (mat == 1) ? g_K : g_V;
    const float* hrow = h + (size_t)row * C_;
    float4 acc = make_float4(0.f, 0.f, 0.f, 0.f);
#pragma unroll 4
    for (int c = 0; c < C_; c++) {
        float  hv = __ldg(hrow + c);
        float4 w  = *(const float4*)(W + (size_t)c * C_ + d);
        acc.x += hv * w.x; acc.y += hv * w.y; acc.z += hv * w.z; acc.w += hv * w.w;
    }
    if (mat == 0) { acc.x *= .25f; acc.y *= .25f; acc.z *= .25f; acc.w *= .25f; }
    *(float4*)(out + (size_t)row * C_ + d) = acc;
}

// ============================================================================
// Kernel 2: bf16 mma.sync edge GEMM + gating + e_out + head-sum/clamp -> g_S
// Persistent 148 CTAs x 512 threads (16 warps). Tile = 128 j x 128 d, K=128.
// Warp w: rows m0=(w>>1)*16, cols n0=(w&1)*64. 3-term bf16 split.
// ============================================================================
__global__ void __launch_bounds__(512, 1)
edge_kernel(const float* __restrict__ e, float* __restrict__ out_e) {
    extern __shared__ char smem[];
    const uint32_t sb = smem_u32(smem);
    const int tid = threadIdx.x, warp = tid >> 5, lane = tid & 31;
    float* sKO = (float*)(smem + SM_KO);
    float* sQ  = (float*)(smem + SM_Q);

    // ---- stage both W splits into swizzled smem (once per CTA) -------------
#pragma unroll
    for (int it = 0; it < 8; it++) {
        int g = tid + 512 * it;                    // 4096 groups of 4 bf16
        int r = g >> 5, c = (g & 31) << 2;
        uint32_t off = swz(r, (uint32_t)c * 2u);
        uint2 a = *(const uint2*)(g_W0T + r * C_ + c);
        STS64(sb + SM_W0 + off, a.x, a.y);
        uint2 bq = *(const uint2*)(g_W1T + r * C_ + c);
        STS64(sb + SM_W1 + off, bq.x, bq.y);
    }

    const int m0 = (warp >> 1) * 16;
    const int n0 = (warp & 1) * 64;

    for (int t = blockIdx.x; t < B_ * N_ * 4; t += gridDim.x) {
        const int bi = t >> 2, j0 = (t & 3) << 7;
        const int b = bi >> 9, i = bi & (N_ - 1);
        const size_t row_base = (size_t)bi * N_ + j0;
        __syncthreads();   // prev iteration's smem consumers done

        // ---- stage e tile (bf16 hi/lo split), K tile, Q row ----------------
        const float4* esrc = (const float4*)e + row_base * 32;
#pragma unroll
        for (int it = 0; it < 8; it++) {
            int g = tid + 512 * it;                // 4096 float4s
            int r = g >> 5, c = (g & 31) << 2;
            float4 v = __ldg(esrc + g);
            __nv_bfloat162 h0 = __floats2bfloat162_rn(v.x, v.y);
            __nv_bfloat162 h1 = __floats2bfloat162_rn(v.z, v.w);
            float2 f0 = __bfloat1622float2(h0), f1 = __bfloat1622float2(h1);
            __nv_bfloat162 l0 = __floats2bfloat162_rn(v.x - f0.x, v.y - f0.y);
            __nv_bfloat162 l1 = __floats2bfloat162_rn(v.z - f1.x, v.w - f1.y);
            uint32_t off = swz(r, (uint32_t)c * 2u);
            STS64(sb + SM_E0 + off, *(uint32_t*)&h0, *(uint32_t*)&h1);
            STS64(sb + SM_E1 + off, *(uint32_t*)&l0, *(uint32_t*)&l1);
        }
        const float4* ksrc = (const float4*)(g_K + ((size_t)b * N_ + j0) * C_);
#pragma unroll
        for (int it = 0; it < 8; it++) {
            int g = tid + 512 * it;
            int r = g >> 5, m = g & 31;
            *(float4*)(sKO + r * 132 + 4 * m) = __ldg(ksrc + g);
        }
        if (tid < 32) ((float4*)sQ)[tid] = ((const float4*)(g_Q + (size_t)bi * C_))[tid];
        __syncthreads();

        // ---- MMA mainloop ---------------------------------------------------
        float acc[8][4];
#pragma unroll
        for (int nt = 0; nt < 8; nt++)
#pragma unroll
            for (int k = 0; k < 4; k++) acc[nt][k] = 0.f;

        const int arow = m0 + (lane & 15);
        const uint32_t a_off = swz(arow, ((uint32_t)(lane >> 4)) * 16u);
#pragma unroll
        for (int ks = 0; ks < 8; ks++) {
            const uint32_t kb = (uint32_t)ks * 32u;
            uint32_t a0[4], a1[4];
            LDSM_X4(a0[0], a0[1], a0[2], a0[3], sb + SM_E0 + a_off + (kb ^ 0u) - (a_off & 0u) + ((kb) ? 0u : 0u) + (( ( (uint32_t)arow & 7u) << 4 ) ^ (((uint32_t)arow & 7u) << 4)) + ( ( (kb ^ ((uint32_t)arow & 7u) << 4) ) - ( ((uint32_t)(lane >> 4)) * 16u ^ (((uint32_t)arow & 7u) << 4) ) ));
            // (the above expression is error-prone; recompute cleanly below)
            {
                uint32_t ao = swz(arow, kb + ((uint32_t)(lane >> 4)) * 16u);
                LDSM_X4(a0[0], a0[1], a0[2], a0[3], sb + SM_E0 + ao);
                LDSM_X4(a1[0], a1[1], a1[2], a1[3], sb + SM_E1 + ao);
            }
#pragma unroll
            for (int nt = 0; nt < 8; nt++) {
                int drow = n0 + nt * 8 + (lane & 7);
                uint32_t bo = swz(drow, kb + (((uint32_t)lane >> 3) & 1u) * 16u);
                uint32_t b0r[2], b1r[2];
                LDSM_X2(b0r[0], b0r[1], sb + SM_W0 + bo);
                LDSM_X2(b1r[0], b1r[1], sb + SM_W1 + bo);
                MMA16816(acc[nt], a0[0], a0[1], a0[2], a0[3], b0r[0], b0r[1]);
                MMA16816(acc[nt], a0[0], a0[1], a0[2], a0[3], b1r[0], b1r[1]);
                MMA16816(acc[nt], a1[0], a1[1], a1[2], a1[3], b0r[0], b0r[1]);
            }
        }

        // ---- epilogue: gate, write e_out into sKO, head-sums -> g_S ---------
        const int r0 = m0 + (lane >> 2);           // tile-local j
        const int r1 = r0 + 8;
        float hs0 = 0.f, hs1 = 0.f;
#pragma unroll
        for (int nt = 0; nt < 8; nt++) {
            int colp = n0 + nt * 8 + 2 * (lane & 3);
            float2 q2 = *(const float2*)(sQ + colp);
            float2 k0 = *(float2*)(sKO + r0 * 132 + colp);
            float2 k1 = *(float2*)(sKO + r1 * 132 + colp);
            float2 e0, e1;
            e0.x = acc[nt][0] * q2.x * k0.x;  e0.y = acc[nt][1] * q2.y * k0.y;
            e1.x = acc[nt][2] * q2.x * k1.x;  e1.y = acc[nt][3] * q2.y * k1.y;
            *(float2*)(sKO + r0 * 132 + colp) = e0;
            *(float2*)(sKO + r1 * 132 + colp) = e1;
            hs0 += e0.x + e0.y;
            hs1 += e1.x + e1.y;
            if (nt & 1) {                           // head complete (2 n-tiles)
                hs0 += __shfl_xor_sync(0xffffffffu, hs0, 1);
                hs0 += __shfl_xor_sync(0xffffffffu, hs0, 2);
                hs1 += __shfl_xor_sync(0xffffffffu, hs1, 1);
                hs1 += __shfl_xor_sync(0xffffffffu, hs1, 2);
                if ((lane & 3) == 0) {
                    int head = (n0 >> 4) + (nt >> 1);
                    float c0 = fminf(fmaxf(hs0, -5.f), 5.f);
                    float c1 = fminf(fmaxf(hs1, -5.f), 5.f);
                    float* sp = g_S + ((size_t)(b * H_ + head) * N_ + i) * N_ + j0;
                    sp[r0] = c0;
                    sp[r1] = c1;
                }
                hs0 = 0.f; hs1 = 0.f;
            }
        }
        __syncthreads();

        // ---- coalesced e_out store ------------------------------------------
        float4* odst = (float4*)out_e + row_base * 32;
#pragma unroll
        for (int it = 0; it < 8; it++) {
            int g = tid + 512 * it;
            int r = g >> 5, m = g & 31;
            odst[g] = *(float4*)(sKO + r * 132 + 4 * m);
        }
    }
}

// ============================================================================
// Kernel 3: exp(g_S) in place + 8-way column-sum partials over i
// ============================================================================
__global__ void expcol_kernel() {
    int bh = blockIdx.x & 15, s8 = blockIdx.x >> 4;
    int j = threadIdx.x;                           // 512 threads
    float* base = g_S + (size_t)bh * N_ * N_;
    float acc = 0.f;
#pragma unroll 4
    for (int ii = 0; ii < 64; ii++) {
        size_t idx = (size_t)(s8 * 64 + ii) * N_ + j;
        float p = __expf(base[idx]);
        base[idx] = p;
        acc += p;
    }
    g_cs[(size_t)(s8 * 16 + bh) * N_ + j] = acc;
}

// ============================================================================
// Kernel 4: h_out fused with softmax normalization.
// CTA = (bh, i-tile of 16); 256 thr = 16 i x 16 c. V slice + inv in smem.
// ============================================================================
__global__ void __launch_bounds__(256)
hout_kernel(float* __restrict__ out_h) {
    __shared__ float sV[N_ * 16];                  // 32 KB
    __shared__ float sInv[N_];
    int bh = blockIdx.x >> 5, i0 = (blockIdx.x & 31) << 4;
    int b = bh >> 3, head = bh & 7;
    int tid = threadIdx.x, ti = tid >> 4, c = tid & 15;

    for (int it = 0; it < 32; it++) {
        int q = tid + 256 * it;                    // 8192 floats
        int j = q >> 4, cc = q & 15;
        sV[q] = __ldg(g_V + ((size_t)b * N_ + j) * C_ + head * 16 + cc);
    }
    for (int t = 0; t < 2; t++) {
        int j = tid + 256 * t;
        float s = 0.f;
#pragma unroll
        for (int s8 = 0; s8 < 8; s8++) s += g_cs[(size_t)(s8 * 16 + bh) * N_ + j];
        sInv[j] = 1.f / s;
    }
    __syncthreads();

    int i = i0 + ti;
    const float4* prow = (const float4*)(g_S + ((size_t)bh * N_ + i) * N_);
    float acc = 0.f;
#pragma unroll 4
    for (int j4 = 0; j4 < 128; j4++) {
        float4 p = __ldg(prow + j4);
        int j = 4 * j4;
        acc += p.x * sInv[j]     * sV[(j)     * 16 + c];
        acc += p.y * sInv[j + 1] * sV[(j + 1) * 16 + c];
        acc += p.z * sInv[j + 2] * sV[(j + 2) * 16 + c];
        acc += p.w * sInv[j + 3] * sV[(j + 3) * 16 + c];
    }
    out_h[((size_t)b * N_ + i) * C_ + head * 16 + c] = acc;
}

// ============================================================================
extern "C" void kernel_launch(void* const* d_in, const int* in_sizes, int n_in,
                              void* d_out, int out_size) {
    const float* h  = (const float*)d_in[0];
    const float* e  = (const float*)d_in[1];
    const float* Wq = (const float*)d_in[2];
    const float* Wk = (const float*)d_in[3];
    const float* Wv = (const float*)d_in[4];
    const float* We = (const float*)d_in[5];

    float* out_h = (float*)d_out;                      // [B,N,C]
    float* out_e = (float*)d_out + B_ * N_ * C_;       // [B,N,N,C]

    cudaFuncSetAttribute(edge_kernel,
                         cudaFuncAttributeMaxDynamicSharedMemorySize, SM_TOT);

    prep_w_kernel<<<64, 256>>>(We);
    qkv_kernel<<<384, 256>>>(h, Wq, Wk, Wv);
    edge_kernel<<<148, 512, SM_TOT>>>(e, out_e);
    expcol_kernel<<<128, 512>>>();
    hout_kernel<<<16 * 32, 256>>>(out_h);
}

// round 9
// speedup vs baseline: 1.7327x; 1.0912x over previous
#include <cuda_runtime.h>
#include <cuda_bf16.h>
#include <cstdint>

#define B_  2
#define N_  512
#define C_  128
#define H_  8
#define NT_ (B_ * N_ * 4)          // 4096 tiles
#define GRID_EDGE 148

// ---------------- scratch (device globals) ----------------------------------
__device__ float g_Q[B_ * N_ * C_];               // pre-scaled by 0.25
__device__ float g_K[B_ * N_ * C_];
__device__ float g_V[B_ * N_ * C_];
__device__ float g_S[B_ * H_ * N_ * N_];          // [b,h,i,j]; holds exp(clamp(s))
__device__ float g_cs[16 * 16 * N_];              // colsum partials [chunk][bh][j]
__device__ __nv_bfloat16 g_W0T[C_ * C_];          // WeT hi split [d][c]
__device__ __nv_bfloat16 g_W1T[C_ * C_];          // WeT lo split [d][c]

// ---------------- helpers ----------------------------------------------------
__device__ __forceinline__ uint32_t smem_u32(const void* p) {
    uint32_t a;
    asm("{ .reg .u64 t; cvta.to.shared.u64 t, %1; cvt.u32.u64 %0, t; }" : "=r"(a) : "l"(p));
    return a;
}
#define LDSM_X4(r0, r1, r2, r3, a) \
    asm volatile("ldmatrix.sync.aligned.m8n8.x4.shared.b16 {%0,%1,%2,%3}, [%4];" \
                 : "=r"(r0), "=r"(r1), "=r"(r2), "=r"(r3) : "r"(a))
#define LDSM_X2(r0, r1, a) \
    asm volatile("ldmatrix.sync.aligned.m8n8.x2.shared.b16 {%0,%1}, [%2];" \
                 : "=r"(r0), "=r"(r1) : "r"(a))
#define MMA16816(c, a0, a1, a2, a3, b0, b1) \
    asm volatile("mma.sync.aligned.m16n8k16.row.col.f32.bf16.bf16.f32 " \
                 "{%0,%1,%2,%3}, {%4,%5,%6,%7}, {%8,%9}, {%0,%1,%2,%3};" \
                 : "+f"((c)[0]), "+f"((c)[1]), "+f"((c)[2]), "+f"((c)[3]) \
                 : "r"(a0), "r"(a1), "r"(a2), "r"(a3), "r"(b0), "r"(b1))
#define STS64(a, u0, u1) \
    asm volatile("st.shared.v2.u32 [%0], {%1, %2};" :: "r"(a), "r"(u0), "r"(u1) : "memory")

// XOR swizzle on 16B chunks within a 256B row (bits 4..6)
__device__ __forceinline__ uint32_t swz(int row, uint32_t cb) {
    return (uint32_t)row * 256u + (cb ^ (((uint32_t)row & 7u) << 4));
}

// dynamic smem byte offsets: W0, W1, then 2 ping-pong (e0,e1) buffers
#define SM_W0   0u
#define SM_W1   32768u
#define SM_EB   65536u             // buf b: E0 = SM_EB + b*65536, E1 = +32768
#define SM_TOT  196608u

// ============================================================================
// Kernel 0: transpose + bf16-split We -> g_W0T/g_W1T [d][c]
// ============================================================================
__global__ void prep_w_kernel(const float* __restrict__ We) {
    int idx = blockIdx.x * 256 + threadIdx.x;      // [0, 16384)
    int d = idx >> 7, c = idx & 127;
    float w = __ldg(We + c * C_ + d);
    __nv_bfloat16 hi = __float2bfloat16_rn(w);
    g_W0T[idx] = hi;
    g_W1T[idx] = __float2bfloat16_rn(w - __bfloat162float(hi));
}

// ============================================================================
// Kernel 1: Q/K/V projections (Q pre-scaled by 0.25)
// ============================================================================
__global__ void qkv_kernel(const float* __restrict__ h, const float* __restrict__ Wq,
                           const float* __restrict__ Wk, const float* __restrict__ Wv) {
    int gid = blockIdx.x * blockDim.x + threadIdx.x;   // [0, 98304)
    int row = gid / 96, q = gid % 96;
    int mat = q >> 5, d = (q & 31) * 4;
    const float* W   = (mat == 0) ? Wq : (mat == 1) ? Wk : Wv;
    float*       out = (mat == 0) ? g_Q : (mat == 1) ? g_K : g_V;
    const float* hrow = h + (size_t)row * C_;
    float4 acc = make_float4(0.f, 0.f, 0.f, 0.f);
#pragma unroll 4
    for (int c = 0; c < C_; c++) {
        float  hv = __ldg(hrow + c);
        float4 w  = *(const float4*)(W + (size_t)c * C_ + d);
        acc.x += hv * w.x; acc.y += hv * w.y; acc.z += hv * w.z; acc.w += hv * w.w;
    }
    if (mat == 0) { acc.x *= .25f; acc.y *= .25f; acc.z *= .25f; acc.w *= .25f; }
    *(float4*)(out + (size_t)row * C_ + d) = acc;
}

// ============================================================================
// Kernel 2: bf16 mma.sync edge GEMM, ping-pong smem + register prefetch.
// Persistent 148 CTAs x 512 threads. Tile = 128 j x 128 d, K=128.
// Warp w: rows m0=(w>>1)*16, cols n0=(w&1)*64. 3-term bf16 split.
// Epilogue reads K/Q from gmem, stores e_out direct (32B sectors), stores
// exp(clamp(head_sum)) into g_S.
// ============================================================================
__device__ __forceinline__ void cvt_sts_tile(uint32_t e0b, uint32_t e1b,
                                             int tid, const float4* pf) {
#pragma unroll
    for (int it = 0; it < 8; it++) {
        int g = tid + 512 * it;
        int r = g >> 5, c = (g & 31) << 2;
        float4 v = pf[it];
        __nv_bfloat162 h0 = __floats2bfloat162_rn(v.x, v.y);
        __nv_bfloat162 h1 = __floats2bfloat162_rn(v.z, v.w);
        float2 f0 = __bfloat1622float2(h0), f1 = __bfloat1622float2(h1);
        __nv_bfloat162 l0 = __floats2bfloat162_rn(v.x - f0.x, v.y - f0.y);
        __nv_bfloat162 l1 = __floats2bfloat162_rn(v.z - f1.x, v.w - f1.y);
        uint32_t off = swz(r, (uint32_t)c * 2u);
        STS64(e0b + off, *(uint32_t*)&h0, *(uint32_t*)&h1);
        STS64(e1b + off, *(uint32_t*)&l0, *(uint32_t*)&l1);
    }
}

__global__ void __launch_bounds__(512, 1)
edge_kernel(const float* __restrict__ e, float* __restrict__ out_e) {
    extern __shared__ char smem[];
    const uint32_t sb = smem_u32(smem);
    const int tid = threadIdx.x, warp = tid >> 5, lane = tid & 31;

    // ---- stage both W splits into swizzled smem (once per CTA) -------------
#pragma unroll
    for (int it = 0; it < 8; it++) {
        int g = tid + 512 * it;                    // 4096 groups of 4 bf16
        int r = g >> 5, c = (g & 31) << 2;
        uint32_t off = swz(r, (uint32_t)c * 2u);
        uint2 a = *(const uint2*)(g_W0T + r * C_ + c);
        STS64(sb + SM_W0 + off, a.x, a.y);
        uint2 bq = *(const uint2*)(g_W1T + r * C_ + c);
        STS64(sb + SM_W1 + off, bq.x, bq.y);
    }

    const int m0 = (warp >> 1) * 16;
    const int n0 = (warp & 1) * 64;

    // ---- prologue: stage first tile into buffer 0 ---------------------------
    int t = blockIdx.x;
    {
        const float4* esrc = (const float4*)e + ((size_t)(t >> 2) * N_ + ((t & 3) << 7)) * 32;
        float4 pf[8];
#pragma unroll
        for (int it = 0; it < 8; it++) pf[it] = __ldg(esrc + tid + 512 * it);
        cvt_sts_tile(sb + SM_EB, sb + SM_EB + 32768u, tid, pf);
    }
    __syncthreads();

    int bsel = 0;
    for (; t < NT_; t += GRID_EDGE) {
        const int bi = t >> 2, j0 = (t & 3) << 7;
        const int b = bi >> 9, i = bi & (N_ - 1);
        const size_t row_base = (size_t)bi * N_ + j0;
        const int tn = t + GRID_EDGE;
        const bool hasn = tn < NT_;

        // ---- prefetch next tile into registers ------------------------------
        float4 pf[8];
        if (hasn) {
            const float4* esrc = (const float4*)e
                + ((size_t)(tn >> 2) * N_ + ((tn & 3) << 7)) * 32;
#pragma unroll
            for (int it = 0; it < 8; it++) pf[it] = __ldg(esrc + tid + 512 * it);
        }

        // ---- MMA mainloop ----------------------------------------------------
        const uint32_t e0b = sb + SM_EB + (uint32_t)bsel * 65536u;
        const uint32_t e1b = e0b + 32768u;
        float acc[8][4];
#pragma unroll
        for (int nt = 0; nt < 8; nt++)
#pragma unroll
            for (int k = 0; k < 4; k++) acc[nt][k] = 0.f;

        const int arow = m0 + (lane & 15);
#pragma unroll
        for (int ks = 0; ks < 8; ks++) {
            const uint32_t kb = (uint32_t)ks * 32u;
            uint32_t a0[4], a1[4];
            uint32_t ao = swz(arow, kb + ((uint32_t)(lane >> 4)) * 16u);
            LDSM_X4(a0[0], a0[1], a0[2], a0[3], e0b + ao);
            LDSM_X4(a1[0], a1[1], a1[2], a1[3], e1b + ao);
#pragma unroll
            for (int nt = 0; nt < 8; nt++) {
                int drow = n0 + nt * 8 + (lane & 7);
                uint32_t bo = swz(drow, kb + (((uint32_t)lane >> 3) & 1u) * 16u);
                uint32_t b0r[2], b1r[2];
                LDSM_X2(b0r[0], b0r[1], sb + SM_W0 + bo);
                LDSM_X2(b1r[0], b1r[1], sb + SM_W1 + bo);
                MMA16816(acc[nt], a0[0], a0[1], a0[2], a0[3], b0r[0], b0r[1]);
                MMA16816(acc[nt], a0[0], a0[1], a0[2], a0[3], b1r[0], b1r[1]);
                MMA16816(acc[nt], a1[0], a1[1], a1[2], a1[3], b0r[0], b1r[1] * 0 + b0r[1]);
            }
        }

        // ---- epilogue: gate with gmem Q/K, direct e_out store, exp(s) -------
        const int r0 = m0 + (lane >> 2);           // tile-local j
        const int r1 = r0 + 8;
        const float* qrow = g_Q + (size_t)bi * C_;
        const float* krow0 = g_K + ((size_t)b * N_ + j0 + r0) * C_;
        const float* krow1 = g_K + ((size_t)b * N_ + j0 + r1) * C_;
        float* orow0 = out_e + (row_base + r0) * C_;
        float* orow1 = out_e + (row_base + r1) * C_;
        float hs0 = 0.f, hs1 = 0.f;
#pragma unroll
        for (int nt = 0; nt < 8; nt++) {
            int colp = n0 + nt * 8 + 2 * (lane & 3);
            float2 q2 = *(const float2*)(qrow + colp);
            float2 k0 = __ldg((const float2*)(krow0 + colp));
            float2 k1 = __ldg((const float2*)(krow1 + colp));
            float2 e0, e1;
            e0.x = acc[nt][0] * q2.x * k0.x;  e0.y = acc[nt][1] * q2.y * k0.y;
            e1.x = acc[nt][2] * q2.x * k1.x;  e1.y = acc[nt][3] * q2.y * k1.y;
            *(float2*)(orow0 + colp) = e0;
            *(float2*)(orow1 + colp) = e1;
            hs0 += e0.x + e0.y;
            hs1 += e1.x + e1.y;
            if (nt & 1) {                           // head complete (2 n-tiles)
                hs0 += __shfl_xor_sync(0xffffffffu, hs0, 1);
                hs0 += __shfl_xor_sync(0xffffffffu, hs0, 2);
                hs1 += __shfl_xor_sync(0xffffffffu, hs1, 1);
                hs1 += __shfl_xor_sync(0xffffffffu, hs1, 2);
                if ((lane & 3) == 0) {
                    int head = (n0 >> 4) + (nt >> 1);
                    float c0 = __expf(fminf(fmaxf(hs0, -5.f), 5.f));
                    float c1 = __expf(fminf(fmaxf(hs1, -5.f), 5.f));
                    float* sp = g_S + ((size_t)(b * H_ + head) * N_ + i) * N_ + j0;
                    sp[r0] = c0;
                    sp[r1] = c1;
                }
                hs0 = 0.f; hs1 = 0.f;
            }
        }

        // ---- convert + store prefetched tile into the other buffer ----------
        if (hasn) {
            uint32_t nb = sb + SM_EB + (uint32_t)(bsel ^ 1) * 65536u;
            cvt_sts_tile(nb, nb + 32768u, tid, pf);
        }
        __syncthreads();
        bsel ^= 1;
    }
}

// ============================================================================
// Kernel 3: column-sum partials of exp'ed g_S (read-only; g_S already exp'ed)
// grid = 16 bh * 16 chunks of 32 i-rows
// ============================================================================
__global__ void colsum_kernel() {
    int bh = blockIdx.x & 15, ch = blockIdx.x >> 4;
    int j = threadIdx.x;                           // 512 threads
    const float* base = g_S + (size_t)bh * N_ * N_ + (size_t)(ch * 32) * N_;
    float acc = 0.f;
#pragma unroll 8
    for (int ii = 0; ii < 32; ii++) acc += __ldg(base + (size_t)ii * N_ + j);
    g_cs[(size_t)(ch * 16 + bh) * N_ + j] = acc;
}

// ============================================================================
// Kernel 4: h_out fused with softmax normalization.
// CTA = (bh, i-tile of 16); 256 thr = 16 i x 16 c. V slice + inv in smem.
// ============================================================================
__global__ void __launch_bounds__(256)
hout_kernel(float* __restrict__ out_h) {
    __shared__ float sV[N_ * 16];                  // 32 KB
    __shared__ float sInv[N_];
    int bh = blockIdx.x >> 5, i0 = (blockIdx.x & 31) << 4;
    int b = bh >> 3, head = bh & 7;
    int tid = threadIdx.x, ti = tid >> 4, c = tid & 15;

    for (int it = 0; it < 32; it++) {
        int q = tid + 256 * it;                    // 8192 floats
        int j = q >> 4, cc = q & 15;
        sV[q] = __ldg(g_V + ((size_t)b * N_ + j) * C_ + head * 16 + cc);
    }
    for (int tt = 0; tt < 2; tt++) {
        int j = tid + 256 * tt;
        float s = 0.f;
#pragma unroll
        for (int ch = 0; ch < 16; ch++) s += g_cs[(size_t)(ch * 16 + bh) * N_ + j];
        sInv[j] = 1.f / s;
    }
    __syncthreads();

    int i = i0 + ti;
    const float4* prow = (const float4*)(g_S + ((size_t)bh * N_ + i) * N_);
    float acc = 0.f;
#pragma unroll 4
    for (int j4 = 0; j4 < 128; j4++) {
        float4 p = __ldg(prow + j4);
        int j = 4 * j4;
        acc += p.x * sInv[j]     * sV[(j)     * 16 + c];
        acc += p.y * sInv[j + 1] * sV[(j + 1) * 16 + c];
        acc += p.z * sInv[j + 2] * sV[(j + 2) * 16 + c];
        acc += p.w * sInv[j + 3] * sV[(j + 3) * 16 + c];
    }
    out_h[((size_t)b * N_ + i) * C_ + head * 16 + c] = acc;
}

// ============================================================================
extern "C" void kernel_launch(void* const* d_in, const int* in_sizes, int n_in,
                              void* d_out, int out_size) {
    const float* h  = (const float*)d_in[0];
    const float* e  = (const float*)d_in[1];
    const float* Wq = (const float*)d_in[2];
    const float* Wk = (const float*)d_in[3];
    const float* Wv = (const float*)d_in[4];
    const float* We = (const float*)d_in[5];

    float* out_h = (float*)d_out;                      // [B,N,C]
    float* out_e = (float*)d_out + B_ * N_ * C_;       // [B,N,N,C]

    cudaFuncSetAttribute(edge_kernel,
                         cudaFuncAttributeMaxDynamicSharedMemorySize, SM_TOT);

    prep_w_kernel<<<64, 256>>>(We);
    qkv_kernel<<<384, 256>>>(h, Wq, Wk, Wv);
    edge_kernel<<<GRID_EDGE, 512, SM_TOT>>>(e, out_e);
    colsum_kernel<<<256, 512>>>();
    hout_kernel<<<16 * 32, 256>>>(out_h);
}

// round 10
// speedup vs baseline: 1.8252x; 1.0534x over previous
#include <cuda_runtime.h>
#include <cuda_bf16.h>
#include <cstdint>

#define B_  2
#define N_  512
#define C_  128
#define H_  8
#define NT_ (B_ * N_ * 8)          // 8192 half-tiles (64 rows each)
#define GRID_EDGE 296

// ---------------- scratch (device globals) ----------------------------------
__device__ float g_Q[B_ * N_ * C_];               // pre-scaled by 0.25
__device__ float g_K[B_ * N_ * C_];
__device__ float g_V[B_ * N_ * C_];
__device__ float g_S[B_ * H_ * N_ * N_];          // [b,h,i,j]; holds exp(clamp(s))
__device__ float g_cs[8 * 16 * N_];               // colsum partials [chunk][bh][j]
__device__ __nv_bfloat16 g_W0T[C_ * C_];          // WeT hi split [d][c]
__device__ __nv_bfloat16 g_W1T[C_ * C_];          // WeT lo split [d][c]

// ---------------- helpers ----------------------------------------------------
__device__ __forceinline__ uint32_t smem_u32(const void* p) {
    uint32_t a;
    asm("{ .reg .u64 t; cvta.to.shared.u64 t, %1; cvt.u32.u64 %0, t; }" : "=r"(a) : "l"(p));
    return a;
}
#define LDSM_X4(r0, r1, r2, r3, a) \
    asm volatile("ldmatrix.sync.aligned.m8n8.x4.shared.b16 {%0,%1,%2,%3}, [%4];" \
                 : "=r"(r0), "=r"(r1), "=r"(r2), "=r"(r3) : "r"(a))
#define LDSM_X2(r0, r1, a) \
    asm volatile("ldmatrix.sync.aligned.m8n8.x2.shared.b16 {%0,%1}, [%2];" \
                 : "=r"(r0), "=r"(r1) : "r"(a))
#define MMA16816(c, a0, a1, a2, a3, b0, b1) \
    asm volatile("mma.sync.aligned.m16n8k16.row.col.f32.bf16.bf16.f32 " \
                 "{%0,%1,%2,%3}, {%4,%5,%6,%7}, {%8,%9}, {%0,%1,%2,%3};" \
                 : "+f"((c)[0]), "+f"((c)[1]), "+f"((c)[2]), "+f"((c)[3]) \
                 : "r"(a0), "r"(a1), "r"(a2), "r"(a3), "r"(b0), "r"(b1))
#define STS64(a, u0, u1) \
    asm volatile("st.shared.v2.u32 [%0], {%1, %2};" :: "r"(a), "r"(u0), "r"(u1) : "memory")

// XOR swizzle on 16B chunks within a 256B row (bits 4..6)
__device__ __forceinline__ uint32_t swz(int row, uint32_t cb) {
    return (uint32_t)row * 256u + (cb ^ (((uint32_t)row & 7u) << 4));
}

// dynamic smem byte offsets: W0, W1, single (e0,e1) tile buffer (64 rows)
#define SM_W0   0u
#define SM_W1   32768u
#define SM_E0   65536u
#define SM_E1   81920u
#define SM_TOT  98304u             // 96 KB -> 2 CTAs/SM

// ============================================================================
// Kernel 0: transpose + bf16-split We -> g_W0T/g_W1T [d][c]
// ============================================================================
__global__ void prep_w_kernel(const float* __restrict__ We) {
    int idx = blockIdx.x * 256 + threadIdx.x;      // [0, 16384)
    int d = idx >> 7, c = idx & 127;
    float w = __ldg(We + c * C_ + d);
    __nv_bfloat16 hi = __float2bfloat16_rn(w);
    g_W0T[idx] = hi;
    g_W1T[idx] = __float2bfloat16_rn(w - __bfloat162float(hi));
}

// ============================================================================
// Kernel 1: Q/K/V projections (Q pre-scaled by 0.25)
// ============================================================================
__global__ void qkv_kernel(const float* __restrict__ h, const float* __restrict__ Wq,
                           const float* __restrict__ Wk, const float* __restrict__ Wv) {
    int gid = blockIdx.x * blockDim.x + threadIdx.x;   // [0, 98304)
    int row = gid / 96, q = gid % 96;
    int mat = q >> 5, d = (q & 31) * 4;
    const float* W   = (mat == 0) ? Wq : (mat == 1) ? Wk : Wv;
    float*       out = (mat == 0) ? g_Q : (mat == 1) ? g_K : g_V;
    const float* hrow = h + (size_t)row * C_;
    float4 acc = make_float4(0.f, 0.f, 0.f, 0.f);
#pragma unroll 4
    for (int c = 0; c < C_; c++) {
        float  hv = __ldg(hrow + c);
        float4 w  = *(const float4*)(W + (size_t)c * C_ + d);
        acc.x += hv * w.x; acc.y += hv * w.y; acc.z += hv * w.z; acc.w += hv * w.w;
    }
    if (mat == 0) { acc.x *= .25f; acc.y *= .25f; acc.z *= .25f; acc.w *= .25f; }
    *(float4*)(out + (size_t)row * C_ + d) = acc;
}

// ============================================================================
// Kernel 2: bf16 mma.sync edge GEMM. 256 threads, 2 CTAs/SM (cross-CTA
// overlap hides epilogue/staging latency). Tile = 64 j x 128 d, K=128.
// Warp w (8 warps): rows m0=(w>>1)*16, cols n0=(w&1)*64. 3-term bf16 split.
// ============================================================================
__device__ __forceinline__ void cvt_sts_tile(uint32_t e0b, uint32_t e1b,
                                             int tid, const float4* pf) {
#pragma unroll
    for (int it = 0; it < 8; it++) {
        int g = tid + 256 * it;                    // [0, 2048)
        int r = g >> 5, c = (g & 31) << 2;
        float4 v = pf[it];
        __nv_bfloat162 h0 = __floats2bfloat162_rn(v.x, v.y);
        __nv_bfloat162 h1 = __floats2bfloat162_rn(v.z, v.w);
        float2 f0 = __bfloat1622float2(h0), f1 = __bfloat1622float2(h1);
        __nv_bfloat162 l0 = __floats2bfloat162_rn(v.x - f0.x, v.y - f0.y);
        __nv_bfloat162 l1 = __floats2bfloat162_rn(v.z - f1.x, v.w - f1.y);
        uint32_t off = swz(r, (uint32_t)c * 2u);
        STS64(e0b + off, *(uint32_t*)&h0, *(uint32_t*)&h1);
        STS64(e1b + off, *(uint32_t*)&l0, *(uint32_t*)&l1);
    }
}

__global__ void __launch_bounds__(256, 2)
edge_kernel(const float* __restrict__ e, float* __restrict__ out_e) {
    extern __shared__ char smem[];
    const uint32_t sb = smem_u32(smem);
    const int tid = threadIdx.x, warp = tid >> 5, lane = tid & 31;

    // ---- stage both W splits into swizzled smem (once per CTA) -------------
#pragma unroll
    for (int it = 0; it < 16; it++) {
        int g = tid + 256 * it;                    // 4096 groups of 4 bf16
        int r = g >> 5, c = (g & 31) << 2;
        uint32_t off = swz(r, (uint32_t)c * 2u);
        uint2 a = *(const uint2*)(g_W0T + r * C_ + c);
        STS64(sb + SM_W0 + off, a.x, a.y);
        uint2 bq = *(const uint2*)(g_W1T + r * C_ + c);
        STS64(sb + SM_W1 + off, bq.x, bq.y);
    }

    const int m0 = (warp >> 1) * 16;               // 0..48
    const int n0 = (warp & 1) * 64;
    const uint32_t e0b = sb + SM_E0, e1b = sb + SM_E1;

    // ---- prologue: stage first tile ------------------------------------------
    int t = blockIdx.x;
    {
        const float4* esrc = (const float4*)e
            + ((size_t)(t >> 3) * N_ + ((t & 7) << 6)) * 32;
        float4 pf[8];
#pragma unroll
        for (int it = 0; it < 8; it++) pf[it] = __ldg(esrc + tid + 256 * it);
        cvt_sts_tile(e0b, e1b, tid, pf);
    }
    __syncthreads();

    for (; t < NT_; t += GRID_EDGE) {
        const int bi = t >> 3, j0 = (t & 7) << 6;
        const int b = bi >> 9, i = bi & (N_ - 1);
        const size_t row_base = (size_t)bi * N_ + j0;
        const int tn = t + GRID_EDGE;
        const bool hasn = tn < NT_;

        // ---- prefetch next tile into registers ------------------------------
        float4 pf[8];
        if (hasn) {
            const float4* esrc = (const float4*)e
                + ((size_t)(tn >> 3) * N_ + ((tn & 7) << 6)) * 32;
#pragma unroll
            for (int it = 0; it < 8; it++) pf[it] = __ldg(esrc + tid + 256 * it);
        }

        // ---- MMA mainloop ----------------------------------------------------
        float acc[8][4];
#pragma unroll
        for (int nt = 0; nt < 8; nt++)
#pragma unroll
            for (int k = 0; k < 4; k++) acc[nt][k] = 0.f;

        const int arow = m0 + (lane & 15);
#pragma unroll
        for (int ks = 0; ks < 8; ks++) {
            const uint32_t kb = (uint32_t)ks * 32u;
            uint32_t a0[4], a1[4];
            uint32_t ao = swz(arow, kb + ((uint32_t)(lane >> 4)) * 16u);
            LDSM_X4(a0[0], a0[1], a0[2], a0[3], e0b + ao);
            LDSM_X4(a1[0], a1[1], a1[2], a1[3], e1b + ao);
#pragma unroll
            for (int nt = 0; nt < 8; nt++) {
                int drow = n0 + nt * 8 + (lane & 7);
                uint32_t bo = swz(drow, kb + (((uint32_t)lane >> 3) & 1u) * 16u);
                uint32_t b0r[2], b1r[2];
                LDSM_X2(b0r[0], b0r[1], sb + SM_W0 + bo);
                LDSM_X2(b1r[0], b1r[1], sb + SM_W1 + bo);
                MMA16816(acc[nt], a0[0], a0[1], a0[2], a0[3], b0r[0], b0r[1]);
                MMA16816(acc[nt], a0[0], a0[1], a0[2], a0[3], b1r[0], b1r[1]);
                MMA16816(acc[nt], a1[0], a1[1], a1[2], a1[3], b0r[0], b0r[1]);
            }
        }

        // ---- epilogue: gate with gmem Q/K, direct e_out store, exp(s) -------
        const int r0 = m0 + (lane >> 2);           // tile-local j in [0,64)
        const int r1 = r0 + 8;
        const float* qrow = g_Q + (size_t)bi * C_;
        const float* krow0 = g_K + ((size_t)b * N_ + j0 + r0) * C_;
        const float* krow1 = g_K + ((size_t)b * N_ + j0 + r1) * C_;
        float* orow0 = out_e + (row_base + r0) * C_;
        float* orow1 = out_e + (row_base + r1) * C_;
        float hs0 = 0.f, hs1 = 0.f;
#pragma unroll
        for (int nt = 0; nt < 8; nt++) {
            int colp = n0 + nt * 8 + 2 * (lane & 3);
            float2 q2 = *(const float2*)(qrow + colp);
            float2 k0 = __ldg((const float2*)(krow0 + colp));
            float2 k1 = __ldg((const float2*)(krow1 + colp));
            float2 e0, e1;
            e0.x = acc[nt][0] * q2.x * k0.x;  e0.y = acc[nt][1] * q2.y * k0.y;
            e1.x = acc[nt][2] * q2.x * k1.x;  e1.y = acc[nt][3] * q2.y * k1.y;
            *(float2*)(orow0 + colp) = e0;
            *(float2*)(orow1 + colp) = e1;
            hs0 += e0.x + e0.y;
            hs1 += e1.x + e1.y;
            if (nt & 1) {                           // head complete (2 n-tiles)
                hs0 += __shfl_xor_sync(0xffffffffu, hs0, 1);
                hs0 += __shfl_xor_sync(0xffffffffu, hs0, 2);
                hs1 += __shfl_xor_sync(0xffffffffu, hs1, 1);
                hs1 += __shfl_xor_sync(0xffffffffu, hs1, 2);
                if ((lane & 3) == 0) {
                    int head = (n0 >> 4) + (nt >> 1);
                    float c0 = __expf(fminf(fmaxf(hs0, -5.f), 5.f));
                    float c1 = __expf(fminf(fmaxf(hs1, -5.f), 5.f));
                    float* sp = g_S + ((size_t)(b * H_ + head) * N_ + i) * N_ + j0;
                    sp[r0] = c0;
                    sp[r1] = c1;
                }
                hs0 = 0.f; hs1 = 0.f;
            }
        }

        // ---- store prefetched tile -------------------------------------------
        __syncthreads();
        if (hasn) cvt_sts_tile(e0b, e1b, tid, pf);
        __syncthreads();
    }
}

// ============================================================================
// Kernel 3: column-sum partials of exp'ed g_S. float4 loads, deep MLP.
// grid = 16 bh * 8 chunks of 64 i-rows; 128 threads = 512 j via float4.
// ============================================================================
__global__ void colsum_kernel() {
    int bh = blockIdx.x & 15, ch = blockIdx.x >> 4;
    int j4 = threadIdx.x;                          // 128 threads
    const float4* base = (const float4*)(g_S + (size_t)bh * N_ * N_
                                         + (size_t)(ch * 64) * N_) + j4;
    float4 acc = make_float4(0.f, 0.f, 0.f, 0.f);
#pragma unroll 16
    for (int ii = 0; ii < 64; ii++) {
        float4 v = __ldg(base + (size_t)ii * (N_ / 4));
        acc.x += v.x; acc.y += v.y; acc.z += v.z; acc.w += v.w;
    }
    *(float4*)(g_cs + (size_t)(ch * 16 + bh) * N_ + 4 * j4) = acc;
}

// ============================================================================
// Kernel 4: h_out fused with softmax normalization.
// CTA = (bh, i-tile of 16); 256 thr = 16 i x 16 c. V slice + inv in smem.
// ============================================================================
__global__ void __launch_bounds__(256)
hout_kernel(float* __restrict__ out_h) {
    __shared__ float sV[N_ * 16];                  // 32 KB
    __shared__ float sInv[N_];
    int bh = blockIdx.x >> 5, i0 = (blockIdx.x & 31) << 4;
    int b = bh >> 3, head = bh & 7;
    int tid = threadIdx.x, ti = tid >> 4, c = tid & 15;

    for (int it = 0; it < 32; it++) {
        int q = tid + 256 * it;                    // 8192 floats
        int j = q >> 4, cc = q & 15;
        sV[q] = __ldg(g_V + ((size_t)b * N_ + j) * C_ + head * 16 + cc);
    }
    for (int tt = 0; tt < 2; tt++) {
        int j = tid + 256 * tt;
        float s = 0.f;
#pragma unroll
        for (int ch = 0; ch < 8; ch++) s += g_cs[(size_t)(ch * 16 + bh) * N_ + j];
        sInv[j] = 1.f / s;
    }
    __syncthreads();

    int i = i0 + ti;
    const float4* prow = (const float4*)(g_S + ((size_t)bh * N_ + i) * N_);
    float acc = 0.f;
#pragma unroll 4
    for (int j4 = 0; j4 < 128; j4++) {
        float4 p = __ldg(prow + j4);
        int j = 4 * j4;
        acc += p.x * sInv[j]     * sV[(j)     * 16 + c];
        acc += p.y * sInv[j + 1] * sV[(j + 1) * 16 + c];
        acc += p.z * sInv[j + 2] * sV[(j + 2) * 16 + c];
        acc += p.w * sInv[j + 3] * sV[(j + 3) * 16 + c];
    }
    out_h[((size_t)b * N_ + i) * C_ + head * 16 + c] = acc;
}

// ============================================================================
extern "C" void kernel_launch(void* const* d_in, const int* in_sizes, int n_in,
                              void* d_out, int out_size) {
    const float* h  = (const float*)d_in[0];
    const float* e  = (const float*)d_in[1];
    const float* Wq = (const float*)d_in[2];
    const float* Wk = (const float*)d_in[3];
    const float* Wv = (const float*)d_in[4];
    const float* We = (const float*)d_in[5];

    float* out_h = (float*)d_out;                      // [B,N,C]
    float* out_e = (float*)d_out + B_ * N_ * C_;       // [B,N,N,C]

    cudaFuncSetAttribute(edge_kernel,
                         cudaFuncAttributeMaxDynamicSharedMemorySize, SM_TOT);

    prep_w_kernel<<<64, 256>>>(We);
    qkv_kernel<<<384, 256>>>(h, Wq, Wk, Wv);
    edge_kernel<<<GRID_EDGE, 256, SM_TOT>>>(e, out_e);
    colsum_kernel<<<128, 128>>>();
    hout_kernel<<<16 * 32, 256>>>(out_h);
}

// round 11
// speedup vs baseline: 2.4084x; 1.3196x over previous
#include <cuda_runtime.h>
#include <cuda_fp16.h>
#include <cstdint>

#define B_  2
#define N_  512
#define C_  128
#define H_  8
#define NT_ (B_ * N_ * 8)          // 8192 tiles (64 rows each)
#define GRID_EDGE 296

// ---------------- scratch (device globals) ----------------------------------
__device__ float g_Q[B_ * N_ * C_];               // pre-scaled by 0.25
__device__ float g_K[B_ * N_ * C_];
__device__ float g_V[B_ * N_ * C_];
__device__ float g_S[B_ * H_ * N_ * N_];          // [b,h,i,j]; holds exp(clamp(s))
__device__ float g_cs[32 * 16 * N_];              // colsum partials [chunk][bh][j]
__device__ __half g_W0T[C_ * C_];                 // WeT fp16 [d][c]

// ---------------- helpers ----------------------------------------------------
__device__ __forceinline__ uint32_t smem_u32(const void* p) {
    uint32_t a;
    asm("{ .reg .u64 t; cvta.to.shared.u64 t, %1; cvt.u32.u64 %0, t; }" : "=r"(a) : "l"(p));
    return a;
}
#define LDSM_X4(r0, r1, r2, r3, a) \
    asm volatile("ldmatrix.sync.aligned.m8n8.x4.shared.b16 {%0,%1,%2,%3}, [%4];" \
                 : "=r"(r0), "=r"(r1), "=r"(r2), "=r"(r3) : "r"(a))
#define MMA16816(c, a0, a1, a2, a3, b0, b1) \
    asm volatile("mma.sync.aligned.m16n8k16.row.col.f32.f16.f16.f32 " \
                 "{%0,%1,%2,%3}, {%4,%5,%6,%7}, {%8,%9}, {%0,%1,%2,%3};" \
                 : "+f"((c)[0]), "+f"((c)[1]), "+f"((c)[2]), "+f"((c)[3]) \
                 : "r"(a0), "r"(a1), "r"(a2), "r"(a3), "r"(b0), "r"(b1))
#define STS64(a, u0, u1) \
    asm volatile("st.shared.v2.u32 [%0], {%1, %2};" :: "r"(a), "r"(u0), "r"(u1) : "memory")

// XOR swizzle on 16B chunks within a 256B row (bits 4..6)
__device__ __forceinline__ uint32_t swz(int row, uint32_t cb) {
    return (uint32_t)row * 256u + (cb ^ (((uint32_t)row & 7u) << 4));
}

// dynamic smem byte offsets: W0, (e0,e1) tile buffer (64 rows, fp16)
#define SM_W0   0u
#define SM_E0   32768u
#define SM_E1   49152u
#define SM_TOT  65536u             // 64 KB -> 2+ CTAs/SM

// ============================================================================
// Kernel 0: transpose + fp16 We -> g_W0T [d][c]
// ============================================================================
__global__ void prep_w_kernel(const float* __restrict__ We) {
    int idx = blockIdx.x * 256 + threadIdx.x;      // [0, 16384)
    int d = idx >> 7, c = idx & 127;
    g_W0T[idx] = __float2half_rn(__ldg(We + c * C_ + d));
}

// ============================================================================
// Kernel 1: Q/K/V projections (Q pre-scaled by 0.25)
// ============================================================================
__global__ void qkv_kernel(const float* __restrict__ h, const float* __restrict__ Wq,
                           const float* __restrict__ Wk, const float* __restrict__ Wv) {
    int gid = blockIdx.x * blockDim.x + threadIdx.x;   // [0, 98304)
    int row = gid / 96, q = gid % 96;
    int mat = q >> 5, d = (q & 31) * 4;
    const float* W   = (mat == 0) ? Wq : (mat == 1) ? Wk : Wv;
    float*       out = (mat == 0) ? g_Q : (mat == 1) ? g_K : g_V;
    const float* hrow = h + (size_t)row * C_;
    float4 acc = make_float4(0.f, 0.f, 0.f, 0.f);
#pragma unroll 4
    for (int c = 0; c < C_; c++) {
        float  hv = __ldg(hrow + c);
        float4 w  = *(const float4*)(W + (size_t)c * C_ + d);
        acc.x += hv * w.x; acc.y += hv * w.y; acc.z += hv * w.z; acc.w += hv * w.w;
    }
    if (mat == 0) { acc.x *= .25f; acc.y *= .25f; acc.z *= .25f; acc.w *= .25f; }
    *(float4*)(out + (size_t)row * C_ + d) = acc;
}

// ============================================================================
// Kernel 2: fp16 mma.sync edge GEMM, 2-term split (e0+e1)*W0.
// 256 threads, 2 CTAs/SM. Tile = 64 j x 128 d, K=128.
// Warp w: m0=(w>>2)*32 (2 m-tiles), n0=(w&3)*32 (4 n-tiles). LDSM.x4 only.
// ============================================================================
__device__ __forceinline__ void cvt_sts_tile(uint32_t e0b, uint32_t e1b,
                                             int tid, const float4* pf) {
#pragma unroll
    for (int it = 0; it < 8; it++) {
        int g = tid + 256 * it;                    // [0, 2048)
        int r = g >> 5, c = (g & 31) << 2;
        float4 v = pf[it];
        __half2 h0 = __float22half2_rn(make_float2(v.x, v.y));
        __half2 h1 = __float22half2_rn(make_float2(v.z, v.w));
        float2 f0 = __half22float2(h0), f1 = __half22float2(h1);
        __half2 l0 = __float22half2_rn(make_float2(v.x - f0.x, v.y - f0.y));
        __half2 l1 = __float22half2_rn(make_float2(v.z - f1.x, v.w - f1.y));
        uint32_t off = swz(r, (uint32_t)c * 2u);
        STS64(e0b + off, *(uint32_t*)&h0, *(uint32_t*)&h1);
        STS64(e1b + off, *(uint32_t*)&l0, *(uint32_t*)&l1);
    }
}

__global__ void __launch_bounds__(256, 2)
edge_kernel(const float* __restrict__ e, float* __restrict__ out_e) {
    extern __shared__ char smem[];
    const uint32_t sb = smem_u32(smem);
    const int tid = threadIdx.x, warp = tid >> 5, lane = tid & 31;

    // ---- stage W0 into swizzled smem (once per CTA) --------------------------
#pragma unroll
    for (int it = 0; it < 16; it++) {
        int g = tid + 256 * it;                    // 4096 groups of 4 fp16
        int r = g >> 5, c = (g & 31) << 2;
        uint32_t off = swz(r, (uint32_t)c * 2u);
        uint2 a = *(const uint2*)(g_W0T + r * C_ + c);
        STS64(sb + SM_W0 + off, a.x, a.y);
    }

    const int m0 = (warp >> 2) * 32;               // 0 or 32
    const int n0 = (warp & 3) * 32;                // 0..96
    const uint32_t e0b = sb + SM_E0, e1b = sb + SM_E1;

    // ---- prologue: stage first tile ------------------------------------------
    int t = blockIdx.x;
    {
        const float4* esrc = (const float4*)e
            + ((size_t)(t >> 3) * N_ + ((t & 7) << 6)) * 32;
        float4 pf[8];
#pragma unroll
        for (int it = 0; it < 8; it++) pf[it] = __ldg(esrc + tid + 256 * it);
        cvt_sts_tile(e0b, e1b, tid, pf);
    }
    __syncthreads();

    for (; t < NT_; t += GRID_EDGE) {
        const int bi = t >> 3, j0 = (t & 7) << 6;
        const int b = bi >> 9, i = bi & (N_ - 1);
        const size_t row_base = (size_t)bi * N_ + j0;
        const int tn = t + GRID_EDGE;
        const bool hasn = tn < NT_;

        // ---- prefetch next tile into registers ------------------------------
        float4 pf[8];
        if (hasn) {
            const float4* esrc = (const float4*)e
                + ((size_t)(tn >> 3) * N_ + ((tn & 7) << 6)) * 32;
#pragma unroll
            for (int it = 0; it < 8; it++) pf[it] = __ldg(esrc + tid + 256 * it);
        }

        // ---- MMA mainloop ----------------------------------------------------
        float acc[2][4][4];
#pragma unroll
        for (int mt = 0; mt < 2; mt++)
#pragma unroll
            for (int nt = 0; nt < 4; nt++)
#pragma unroll
                for (int k = 0; k < 4; k++) acc[mt][nt][k] = 0.f;

#pragma unroll
        for (int ks = 0; ks < 8; ks++) {
            const uint32_t kb = (uint32_t)ks * 32u;
            uint32_t a0[2][4], a1[2][4], bf[2][4];
#pragma unroll
            for (int mt = 0; mt < 2; mt++) {
                int arow = m0 + mt * 16 + (lane & 15);
                uint32_t ao = swz(arow, kb + ((uint32_t)(lane >> 4)) * 16u);
                LDSM_X4(a0[mt][0], a0[mt][1], a0[mt][2], a0[mt][3], e0b + ao);
                LDSM_X4(a1[mt][0], a1[mt][1], a1[mt][2], a1[mt][3], e1b + ao);
            }
#pragma unroll
            for (int ntp = 0; ntp < 2; ntp++) {
                int drow = n0 + ntp * 16 + ((lane >> 4) << 3) + (lane & 7);
                uint32_t bo = swz(drow, kb + (((uint32_t)lane >> 3) & 1u) * 16u);
                LDSM_X4(bf[ntp][0], bf[ntp][1], bf[ntp][2], bf[ntp][3],
                        sb + SM_W0 + bo);
            }
#pragma unroll
            for (int mt = 0; mt < 2; mt++)
#pragma unroll
                for (int nt = 0; nt < 4; nt++) {
                    uint32_t bb0 = bf[nt >> 1][(nt & 1) * 2];
                    uint32_t bb1 = bf[nt >> 1][(nt & 1) * 2 + 1];
                    MMA16816(acc[mt][nt], a0[mt][0], a0[mt][1], a0[mt][2], a0[mt][3], bb0, bb1);
                    MMA16816(acc[mt][nt], a1[mt][0], a1[mt][1], a1[mt][2], a1[mt][3], bb0, bb1);
                }
        }

        // ---- epilogue: gate with gmem Q/K, direct e_out store, exp(s) -------
        const float* qrow = g_Q + (size_t)bi * C_;
#pragma unroll
        for (int mt = 0; mt < 2; mt++) {
            const int r0 = m0 + mt * 16 + (lane >> 2);   // tile-local j
            const int r1 = r0 + 8;
            const float* krow0 = g_K + ((size_t)b * N_ + j0 + r0) * C_;
            const float* krow1 = g_K + ((size_t)b * N_ + j0 + r1) * C_;
            float* orow0 = out_e + (row_base + r0) * C_;
            float* orow1 = out_e + (row_base + r1) * C_;
            float hs0 = 0.f, hs1 = 0.f;
#pragma unroll
            for (int nt = 0; nt < 4; nt++) {
                int colp = n0 + nt * 8 + 2 * (lane & 3);
                float2 q2 = *(const float2*)(qrow + colp);
                float2 k0 = __ldg((const float2*)(krow0 + colp));
                float2 k1 = __ldg((const float2*)(krow1 + colp));
                float2 e0, e1;
                e0.x = acc[mt][nt][0] * q2.x * k0.x;  e0.y = acc[mt][nt][1] * q2.y * k0.y;
                e1.x = acc[mt][nt][2] * q2.x * k1.x;  e1.y = acc[mt][nt][3] * q2.y * k1.y;
                *(float2*)(orow0 + colp) = e0;
                *(float2*)(orow1 + colp) = e1;
                hs0 += e0.x + e0.y;
                hs1 += e1.x + e1.y;
                if (nt & 1) {                        // head complete (2 n-tiles)
                    hs0 += __shfl_xor_sync(0xffffffffu, hs0, 1);
                    hs0 += __shfl_xor_sync(0xffffffffu, hs0, 2);
                    hs1 += __shfl_xor_sync(0xffffffffu, hs1, 1);
                    hs1 += __shfl_xor_sync(0xffffffffu, hs1, 2);
                    if ((lane & 3) == 0) {
                        int head = (n0 >> 4) + (nt >> 1);
                        float c0 = __expf(fminf(fmaxf(hs0, -5.f), 5.f));
                        float c1 = __expf(fminf(fmaxf(hs1, -5.f), 5.f));
                        float* sp = g_S + ((size_t)(b * H_ + head) * N_ + i) * N_ + j0;
                        sp[r0] = c0;
                        sp[r1] = c1;
                    }
                    hs0 = 0.f; hs1 = 0.f;
                }
            }
        }

        // ---- store prefetched tile -------------------------------------------
        __syncthreads();
        if (hasn) cvt_sts_tile(e0b, e1b, tid, pf);
        __syncthreads();
    }
}

// ============================================================================
// Kernel 3: column-sum partials of exp'ed g_S. float4 loads, deep MLP.
// grid = 16 bh * 32 chunks of 16 i-rows; 128 threads = 512 j via float4.
// ============================================================================
__global__ void colsum_kernel() {
    int bh = blockIdx.x & 15, ch = blockIdx.x >> 4;
    int j4 = threadIdx.x;                          // 128 threads
    const float4* base = (const float4*)(g_S + (size_t)bh * N_ * N_
                                         + (size_t)(ch * 16) * N_) + j4;
    float4 acc = make_float4(0.f, 0.f, 0.f, 0.f);
#pragma unroll 16
    for (int ii = 0; ii < 16; ii++) {
        float4 v = __ldg(base + (size_t)ii * (N_ / 4));
        acc.x += v.x; acc.y += v.y; acc.z += v.z; acc.w += v.w;
    }
    *(float4*)(g_cs + (size_t)(ch * 16 + bh) * N_ + 4 * j4) = acc;
}

// ============================================================================
// Kernel 4: h_out fused with softmax normalization.
// CTA = (bh, i-tile of 16); 256 thr = 16 i x 16 c. V slice + inv in smem.
// ============================================================================
__global__ void __launch_bounds__(256)
hout_kernel(float* __restrict__ out_h) {
    __shared__ float sV[N_ * 16];                  // 32 KB
    __shared__ float sInv[N_];
    int bh = blockIdx.x >> 5, i0 = (blockIdx.x & 31) << 4;
    int b = bh >> 3, head = bh & 7;
    int tid = threadIdx.x, ti = tid >> 4, c = tid & 15;

    for (int it = 0; it < 32; it++) {
        int q = tid + 256 * it;                    // 8192 floats
        int j = q >> 4, cc = q & 15;
        sV[q] = __ldg(g_V + ((size_t)b * N_ + j) * C_ + head * 16 + cc);
    }
    for (int tt = 0; tt < 2; tt++) {
        int j = tid + 256 * tt;
        float s = 0.f;
#pragma unroll
        for (int ch = 0; ch < 32; ch++) s += g_cs[(size_t)(ch * 16 + bh) * N_ + j];
        sInv[j] = 1.f / s;
    }
    __syncthreads();

    int i = i0 + ti;
    const float4* prow = (const float4*)(g_S + ((size_t)bh * N_ + i) * N_);
    float acc = 0.f;
#pragma unroll 4
    for (int j4 = 0; j4 < 128; j4++) {
        float4 p = __ldg(prow + j4);
        int j = 4 * j4;
        acc += p.x * sInv[j]     * sV[(j)     * 16 + c];
        acc += p.y * sInv[j + 1] * sV[(j + 1) * 16 + c];
        acc += p.z * sInv[j + 2] * sV[(j + 2) * 16 + c];
        acc += p.w * sInv[j + 3] * sV[(j + 3) * 16 + c];
    }
    out_h[((size_t)b * N_ + i) * C_ + head * 16 + c] = acc;
}

// ============================================================================
extern "C" void kernel_launch(void* const* d_in, const int* in_sizes, int n_in,
                              void* d_out, int out_size) {
    const float* h  = (const float*)d_in[0];
    const float* e  = (const float*)d_in[1];
    const float* Wq = (const float*)d_in[2];
    const float* Wk = (const float*)d_in[3];
    const float* Wv = (const float*)d_in[4];
    const float* We = (const float*)d_in[5];

    float* out_h = (float*)d_out;                      // [B,N,C]
    float* out_e = (float*)d_out + B_ * N_ * C_;       // [B,N,N,C]

    cudaFuncSetAttribute(edge_kernel,
                         cudaFuncAttributeMaxDynamicSharedMemorySize, SM_TOT);

    prep_w_kernel<<<64, 256>>>(We);
    qkv_kernel<<<384, 256>>>(h, Wq, Wk, Wv);
    edge_kernel<<<GRID_EDGE, 256, SM_TOT>>>(e, out_e);
    colsum_kernel<<<512, 128>>>();
    hout_kernel<<<16 * 32, 256>>>(out_h);
}

// round 12
// speedup vs baseline: 2.5206x; 1.0466x over previous
#include <cuda_runtime.h>
#include <cuda_fp16.h>
#include <cstdint>

#define B_  2
#define N_  512
#define C_  128
#define H_  8
#define NT_ (B_ * N_ * 8)          // 8192 tiles (64 rows each)
#define GRID_EDGE 296

// ---------------- scratch (device globals) ----------------------------------
__device__ float g_Q[B_ * N_ * C_];               // pre-scaled by 0.25
__device__ float g_K[B_ * N_ * C_];
__device__ float g_V[B_ * N_ * C_];
__device__ float g_S[B_ * H_ * N_ * N_];          // [b,h,i,j]; holds exp(clamp(s))
__device__ float g_cs[32 * 16 * N_];              // colsum partials [chunk][bh][j]
__device__ __half g_W0T[C_ * C_];                 // WeT fp16 [d][c]

// ---------------- helpers ----------------------------------------------------
__device__ __forceinline__ uint32_t smem_u32(const void* p) {
    uint32_t a;
    asm("{ .reg .u64 t; cvta.to.shared.u64 t, %1; cvt.u32.u64 %0, t; }" : "=r"(a) : "l"(p));
    return a;
}
#define LDSM_X4(r0, r1, r2, r3, a) \
    asm volatile("ldmatrix.sync.aligned.m8n8.x4.shared.b16 {%0,%1,%2,%3}, [%4];" \
                 : "=r"(r0), "=r"(r1), "=r"(r2), "=r"(r3) : "r"(a))
#define MMA16816(c, a0, a1, a2, a3, b0, b1) \
    asm volatile("mma.sync.aligned.m16n8k16.row.col.f32.f16.f16.f32 " \
                 "{%0,%1,%2,%3}, {%4,%5,%6,%7}, {%8,%9}, {%0,%1,%2,%3};" \
                 : "+f"((c)[0]), "+f"((c)[1]), "+f"((c)[2]), "+f"((c)[3]) \
                 : "r"(a0), "r"(a1), "r"(a2), "r"(a3), "r"(b0), "r"(b1))
#define STS64(a, u0, u1) \
    asm volatile("st.shared.v2.u32 [%0], {%1, %2};" :: "r"(a), "r"(u0), "r"(u1) : "memory")

// XOR swizzle on 16B chunks within a 256B row (bits 4..6)
__device__ __forceinline__ uint32_t swz(int row, uint32_t cb) {
    return (uint32_t)row * 256u + (cb ^ (((uint32_t)row & 7u) << 4));
}

// dynamic smem byte offsets: W0, single e tile buffer (64 rows, fp16)
#define SM_W0   0u
#define SM_E0   32768u
#define SM_TOT  49152u             // 48 KB -> 2 CTAs/SM easily

// ============================================================================
// Kernel 0: transpose + fp16 We -> g_W0T [d][c]
// ============================================================================
__global__ void prep_w_kernel(const float* __restrict__ We) {
    int idx = blockIdx.x * 256 + threadIdx.x;      // [0, 16384)
    int d = idx >> 7, c = idx & 127;
    g_W0T[idx] = __float2half_rn(__ldg(We + c * C_ + d));
}

// ============================================================================
// Kernel 1: Q/K/V projections (Q pre-scaled by 0.25)
// ============================================================================
__global__ void qkv_kernel(const float* __restrict__ h, const float* __restrict__ Wq,
                           const float* __restrict__ Wk, const float* __restrict__ Wv) {
    int gid = blockIdx.x * blockDim.x + threadIdx.x;   // [0, 98304)
    int row = gid / 96, q = gid % 96;
    int mat = q >> 5, d = (q & 31) * 4;
    const float* W   = (mat == 0) ? Wq : (mat == 1) ? Wk : Wv;
    float*       out = (mat == 0) ? g_Q : (mat == 1) ? g_K : g_V;
    const float* hrow = h + (size_t)row * C_;
    float4 acc = make_float4(0.f, 0.f, 0.f, 0.f);
#pragma unroll 4
    for (int c = 0; c < C_; c++) {
        float  hv = __ldg(hrow + c);
        float4 w  = *(const float4*)(W + (size_t)c * C_ + d);
        acc.x += hv * w.x; acc.y += hv * w.y; acc.z += hv * w.z; acc.w += hv * w.w;
    }
    if (mat == 0) { acc.x *= .25f; acc.y *= .25f; acc.z *= .25f; acc.w *= .25f; }
    *(float4*)(out + (size_t)row * C_ + d) = acc;
}

// ============================================================================
// Kernel 2: fp16 mma.sync edge GEMM, single-term (fp16 e x fp16 W).
// 256 threads, 2 CTAs/SM. Tile = 64 j x 128 d, K=128.
// Warp w: m0=(w>>2)*32 (2 m-tiles), n0=(w&3)*32 (4 n-tiles). LDSM.x4 only.
// ============================================================================
__device__ __forceinline__ void cvt_sts_tile(uint32_t e0b, int tid, const float4* pf) {
#pragma unroll
    for (int it = 0; it < 8; it++) {
        int g = tid + 256 * it;                    // [0, 2048)
        int r = g >> 5, c = (g & 31) << 2;
        float4 v = pf[it];
        __half2 h0 = __float22half2_rn(make_float2(v.x, v.y));
        __half2 h1 = __float22half2_rn(make_float2(v.z, v.w));
        uint32_t off = swz(r, (uint32_t)c * 2u);
        STS64(e0b + off, *(uint32_t*)&h0, *(uint32_t*)&h1);
    }
}

__global__ void __launch_bounds__(256, 2)
edge_kernel(const float* __restrict__ e, float* __restrict__ out_e) {
    extern __shared__ char smem[];
    const uint32_t sb = smem_u32(smem);
    const int tid = threadIdx.x, warp = tid >> 5, lane = tid & 31;

    // ---- stage W0 into swizzled smem (once per CTA) --------------------------
#pragma unroll
    for (int it = 0; it < 16; it++) {
        int g = tid + 256 * it;                    // 4096 groups of 4 fp16
        int r = g >> 5, c = (g & 31) << 2;
        uint32_t off = swz(r, (uint32_t)c * 2u);
        uint2 a = *(const uint2*)(g_W0T + r * C_ + c);
        STS64(sb + SM_W0 + off, a.x, a.y);
    }

    const int m0 = (warp >> 2) * 32;               // 0 or 32
    const int n0 = (warp & 3) * 32;                // 0..96
    const uint32_t e0b = sb + SM_E0;

    // ---- prologue: stage first tile ------------------------------------------
    int t = blockIdx.x;
    {
        const float4* esrc = (const float4*)e
            + ((size_t)(t >> 3) * N_ + ((t & 7) << 6)) * 32;
        float4 pf[8];
#pragma unroll
        for (int it = 0; it < 8; it++) pf[it] = __ldg(esrc + tid + 256 * it);
        cvt_sts_tile(e0b, tid, pf);
    }
    __syncthreads();

    for (; t < NT_; t += GRID_EDGE) {
        const int bi = t >> 3, j0 = (t & 7) << 6;
        const int b = bi >> 9, i = bi & (N_ - 1);
        const size_t row_base = (size_t)bi * N_ + j0;
        const int tn = t + GRID_EDGE;
        const bool hasn = tn < NT_;

        // ---- prefetch next tile into registers ------------------------------
        float4 pf[8];
        if (hasn) {
            const float4* esrc = (const float4*)e
                + ((size_t)(tn >> 3) * N_ + ((tn & 7) << 6)) * 32;
#pragma unroll
            for (int it = 0; it < 8; it++) pf[it] = __ldg(esrc + tid + 256 * it);
        }

        // ---- MMA mainloop ----------------------------------------------------
        float acc[2][4][4];
#pragma unroll
        for (int mt = 0; mt < 2; mt++)
#pragma unroll
            for (int nt = 0; nt < 4; nt++)
#pragma unroll
                for (int k = 0; k < 4; k++) acc[mt][nt][k] = 0.f;

#pragma unroll
        for (int ks = 0; ks < 8; ks++) {
            const uint32_t kb = (uint32_t)ks * 32u;
            uint32_t a0[2][4], bf[2][4];
#pragma unroll
            for (int mt = 0; mt < 2; mt++) {
                int arow = m0 + mt * 16 + (lane & 15);
                uint32_t ao = swz(arow, kb + ((uint32_t)(lane >> 4)) * 16u);
                LDSM_X4(a0[mt][0], a0[mt][1], a0[mt][2], a0[mt][3], e0b + ao);
            }
#pragma unroll
            for (int ntp = 0; ntp < 2; ntp++) {
                int drow = n0 + ntp * 16 + ((lane >> 4) << 3) + (lane & 7);
                uint32_t bo = swz(drow, kb + (((uint32_t)lane >> 3) & 1u) * 16u);
                LDSM_X4(bf[ntp][0], bf[ntp][1], bf[ntp][2], bf[ntp][3],
                        sb + SM_W0 + bo);
            }
#pragma unroll
            for (int mt = 0; mt < 2; mt++)
#pragma unroll
                for (int nt = 0; nt < 4; nt++) {
                    uint32_t bb0 = bf[nt >> 1][(nt & 1) * 2];
                    uint32_t bb1 = bf[nt >> 1][(nt & 1) * 2 + 1];
                    MMA16816(acc[mt][nt], a0[mt][0], a0[mt][1], a0[mt][2], a0[mt][3], bb0, bb1);
                }
        }

        // ---- epilogue: gate with gmem Q/K, direct e_out store, exp(s) -------
        const float* qrow = g_Q + (size_t)bi * C_;
#pragma unroll
        for (int mt = 0; mt < 2; mt++) {
            const int r0 = m0 + mt * 16 + (lane >> 2);   // tile-local j
            const int r1 = r0 + 8;
            const float* krow0 = g_K + ((size_t)b * N_ + j0 + r0) * C_;
            const float* krow1 = g_K + ((size_t)b * N_ + j0 + r1) * C_;
            float* orow0 = out_e + (row_base + r0) * C_;
            float* orow1 = out_e + (row_base + r1) * C_;
            float hs0 = 0.f, hs1 = 0.f;
#pragma unroll
            for (int nt = 0; nt < 4; nt++) {
                int colp = n0 + nt * 8 + 2 * (lane & 3);
                float2 q2 = *(const float2*)(qrow + colp);
                float2 k0 = __ldg((const float2*)(krow0 + colp));
                float2 k1 = __ldg((const float2*)(krow1 + colp));
                float2 e0, e1;
                e0.x = acc[mt][nt][0] * q2.x * k0.x;  e0.y = acc[mt][nt][1] * q2.y * k0.y;
                e1.x = acc[mt][nt][2] * q2.x * k1.x;  e1.y = acc[mt][nt][3] * q2.y * k1.y;
                *(float2*)(orow0 + colp) = e0;
                *(float2*)(orow1 + colp) = e1;
                hs0 += e0.x + e0.y;
                hs1 += e1.x + e1.y;
                if (nt & 1) {                        // head complete (2 n-tiles)
                    hs0 += __shfl_xor_sync(0xffffffffu, hs0, 1);
                    hs0 += __shfl_xor_sync(0xffffffffu, hs0, 2);
                    hs1 += __shfl_xor_sync(0xffffffffu, hs1, 1);
                    hs1 += __shfl_xor_sync(0xffffffffu, hs1, 2);
                    if ((lane & 3) == 0) {
                        int head = (n0 >> 4) + (nt >> 1);
                        float c0 = __expf(fminf(fmaxf(hs0, -5.f), 5.f));
                        float c1 = __expf(fminf(fmaxf(hs1, -5.f), 5.f));
                        float* sp = g_S + ((size_t)(b * H_ + head) * N_ + i) * N_ + j0;
                        sp[r0] = c0;
                        sp[r1] = c1;
                    }
                    hs0 = 0.f; hs1 = 0.f;
                }
            }
        }

        // ---- store prefetched tile -------------------------------------------
        __syncthreads();
        if (hasn) cvt_sts_tile(e0b, tid, pf);
        __syncthreads();
    }
}

// ============================================================================
// Kernel 3: column-sum partials of exp'ed g_S. float4 loads, deep MLP.
// grid = 16 bh * 32 chunks of 16 i-rows; 128 threads = 512 j via float4.
// ============================================================================
__global__ void colsum_kernel() {
    int bh = blockIdx.x & 15, ch = blockIdx.x >> 4;
    int j4 = threadIdx.x;                          // 128 threads
    const float4* base = (const float4*)(g_S + (size_t)bh * N_ * N_
                                         + (size_t)(ch * 16) * N_) + j4;
    float4 acc = make_float4(0.f, 0.f, 0.f, 0.f);
#pragma unroll 16
    for (int ii = 0; ii < 16; ii++) {
        float4 v = __ldg(base + (size_t)ii * (N_ / 4));
        acc.x += v.x; acc.y += v.y; acc.z += v.z; acc.w += v.w;
    }
    *(float4*)(g_cs + (size_t)(ch * 16 + bh) * N_ + 4 * j4) = acc;
}

// ============================================================================
// Kernel 4: h_out fused with softmax normalization.
// CTA = (bh, i-tile of 16); 256 thr = 16 i x 16 c. V slice + inv in smem.
// ============================================================================
__global__ void __launch_bounds__(256)
hout_kernel(float* __restrict__ out_h) {
    __shared__ float sV[N_ * 16];                  // 32 KB
    __shared__ float sInv[N_];
    int bh = blockIdx.x >> 5, i0 = (blockIdx.x & 31) << 4;
    int b = bh >> 3, head = bh & 7;
    int tid = threadIdx.x, ti = tid >> 4, c = tid & 15;

    for (int it = 0; it < 32; it++) {
        int q = tid + 256 * it;                    // 8192 floats
        int j = q >> 4, cc = q & 15;
        sV[q] = __ldg(g_V + ((size_t)b * N_ + j) * C_ + head * 16 + cc);
    }
    for (int tt = 0; tt < 2; tt++) {
        int j = tid + 256 * tt;
        float s = 0.f;
#pragma unroll
        for (int ch = 0; ch < 32; ch++) s += g_cs[(size_t)(ch * 16 + bh) * N_ + j];
        sInv[j] = 1.f / s;
    }
    __syncthreads();

    int i = i0 + ti;
    const float4* prow = (const float4*)(g_S + ((size_t)bh * N_ + i) * N_);
    float acc = 0.f;
#pragma unroll 4
    for (int j4 = 0; j4 < 128; j4++) {
        float4 p = __ldg(prow + j4);
        int j = 4 * j4;
        acc += p.x * sInv[j]     * sV[(j)     * 16 + c];
        acc += p.y * sInv[j + 1] * sV[(j + 1) * 16 + c];
        acc += p.z * sInv[j + 2] * sV[(j + 2) * 16 + c];
        acc += p.w * sInv[j + 3] * sV[(j + 3) * 16 + c];
    }
    out_h[((size_t)b * N_ + i) * C_ + head * 16 + c] = acc;
}

// ============================================================================
extern "C" void kernel_launch(void* const* d_in, const int* in_sizes, int n_in,
                              void* d_out, int out_size) {
    const float* h  = (const float*)d_in[0];
    const float* e  = (const float*)d_in[1];
    const float* Wq = (const float*)d_in[2];
    const float* Wk = (const float*)d_in[3];
    const float* Wv = (const float*)d_in[4];
    const float* We = (const float*)d_in[5];

    float* out_h = (float*)d_out;                      // [B,N,C]
    float* out_e = (float*)d_out + B_ * N_ * C_;       // [B,N,N,C]

    cudaFuncSetAttribute(edge_kernel,
                         cudaFuncAttributeMaxDynamicSharedMemorySize, SM_TOT);

    prep_w_kernel<<<64, 256>>>(We);
    qkv_kernel<<<384, 256>>>(h, Wq, Wk, Wv);
    edge_kernel<<<GRID_EDGE, 256, SM_TOT>>>(e, out_e);
    colsum_kernel<<<512, 128>>>();
    hout_kernel<<<16 * 32, 256>>>(out_h);
}

// round 13
// speedup vs baseline: 2.6516x; 1.0520x over previous
#include <cuda_runtime.h>
#include <cuda_fp16.h>
#include <cstdint>

#define B_  2
#define N_  512
#define C_  128
#define H_  8
#define NT_ (B_ * N_ * 8)          // 8192 tiles (64 rows each)
#define GRID_EDGE 296

// ---------------- scratch (device globals) ----------------------------------
__device__ float g_Q[B_ * N_ * C_];               // pre-scaled by 0.25
__device__ float g_K[B_ * N_ * C_];
__device__ float g_V[B_ * N_ * C_];
__device__ float g_S[B_ * H_ * N_ * N_];          // [b,h,i,j]; holds exp(clamp(s))
__device__ float g_cs[32 * 16 * N_];              // colsum partials [chunk][bh][j]
__device__ __half g_W0T[C_ * C_];                 // WeT fp16 [d][c]

// ---------------- helpers ----------------------------------------------------
__device__ __forceinline__ uint32_t smem_u32(const void* p) {
    uint32_t a;
    asm("{ .reg .u64 t; cvta.to.shared.u64 t, %1; cvt.u32.u64 %0, t; }" : "=r"(a) : "l"(p));
    return a;
}
#define LDSM_X4(r0, r1, r2, r3, a) \
    asm volatile("ldmatrix.sync.aligned.m8n8.x4.shared.b16 {%0,%1,%2,%3}, [%4];" \
                 : "=r"(r0), "=r"(r1), "=r"(r2), "=r"(r3) : "r"(a))
#define MMA16816(c, a0, a1, a2, a3, b0, b1) \
    asm volatile("mma.sync.aligned.m16n8k16.row.col.f32.f16.f16.f32 " \
                 "{%0,%1,%2,%3}, {%4,%5,%6,%7}, {%8,%9}, {%0,%1,%2,%3};" \
                 : "+f"((c)[0]), "+f"((c)[1]), "+f"((c)[2]), "+f"((c)[3]) \
                 : "r"(a0), "r"(a1), "r"(a2), "r"(a3), "r"(b0), "r"(b1))
#define STS64(a, u0, u1) \
    asm volatile("st.shared.v2.u32 [%0], {%1, %2};" :: "r"(a), "r"(u0), "r"(u1) : "memory")
#define LDS128F(v, a) \
    asm volatile("ld.shared.v4.f32 {%0,%1,%2,%3}, [%4];" \
                 : "=f"((v).x), "=f"((v).y), "=f"((v).z), "=f"((v).w) : "r"(a))
#define LDS64F(v, a) \
    asm volatile("ld.shared.v2.f32 {%0,%1}, [%2];" : "=f"((v).x), "=f"((v).y) : "r"(a))
#define CP_ASYNC16(s, g) \
    asm volatile("cp.async.cg.shared.global [%0], [%1], 16;" :: "r"(s), "l"(g) : "memory")
#define CP_COMMIT()  asm volatile("cp.async.commit_group;" ::: "memory")
#define CP_WAIT0()   asm volatile("cp.async.wait_group 0;" ::: "memory")

// XOR swizzle on 16B chunks within a 256B row (bits 4..6)
__device__ __forceinline__ uint32_t swz(int row, uint32_t cb) {
    return (uint32_t)row * 256u + (cb ^ (((uint32_t)row & 7u) << 4));
}

// dynamic smem byte offsets
#define SM_E16  0u                 // 64x128 fp16 swizzled (16 KB)
#define SM_E32  16384u             // fp32 e staging / initial W staging (32 KB)
#define SM_K    49152u             // 64 rows x 132 floats padded (33792 B)
#define SM_TOT  83968u             // ~82 KB -> 2 CTAs/SM

// ============================================================================
// Kernel 0: transpose + fp16 We -> g_W0T [d][c]
// ============================================================================
__global__ void prep_w_kernel(const float* __restrict__ We) {
    int idx = blockIdx.x * 256 + threadIdx.x;      // [0, 16384)
    int d = idx >> 7, c = idx & 127;
    g_W0T[idx] = __float2half_rn(__ldg(We + c * C_ + d));
}

// ============================================================================
// Kernel 1: Q/K/V projections (Q pre-scaled by 0.25)
// ============================================================================
__global__ void qkv_kernel(const float* __restrict__ h, const float* __restrict__ Wq,
                           const float* __restrict__ Wk, const float* __restrict__ Wv) {
    int gid = blockIdx.x * blockDim.x + threadIdx.x;   // [0, 98304)
    int row = gid / 96, q = gid % 96;
    int mat = q >> 5, d = (q & 31) * 4;
    const float* W   = (mat == 0) ? Wq : (mat == 1) ? Wk : Wv;
    float*       out = (mat == 0) ? g_Q : (mat == 1) ? g_K : g_V;
    const float* hrow = h + (size_t)row * C_;
    float4 acc = make_float4(0.f, 0.f, 0.f, 0.f);
#pragma unroll 4
    for (int c = 0; c < C_; c++) {
        float  hv = __ldg(hrow + c);
        float4 w  = *(const float4*)(W + (size_t)c * C_ + d);
        acc.x += hv * w.x; acc.y += hv * w.y; acc.z += hv * w.z; acc.w += hv * w.w;
    }
    if (mat == 0) { acc.x *= .25f; acc.y *= .25f; acc.z *= .25f; acc.w *= .25f; }
    *(float4*)(out + (size_t)row * C_ + d) = acc;
}

// ============================================================================
// Kernel 2 helpers
// ============================================================================
__device__ __forceinline__ void cp_e_tile(uint32_t sb, const float* e, int t, int tid) {
    const float4* esrc = (const float4*)e
        + ((size_t)(t >> 3) * N_ + ((t & 7) << 6)) * 32;
#pragma unroll
    for (int it = 0; it < 8; it++) {
        int g = tid + 256 * it;
        CP_ASYNC16(sb + SM_E32 + (uint32_t)g * 16u, (const void*)(esrc + g));
    }
}
__device__ __forceinline__ void cp_k_tile(uint32_t sb, int t, int tid) {
    int bi = t >> 3, j0 = (t & 7) << 6, b = bi >> 9;
    const float4* ksrc = (const float4*)(g_K + ((size_t)b * N_ + j0) * C_);
#pragma unroll
    for (int it = 0; it < 8; it++) {
        int g = tid + 256 * it;
        int r = g >> 5, m = g & 31;
        CP_ASYNC16(sb + SM_K + (uint32_t)(r * 528 + m * 16), (const void*)(ksrc + g));
    }
}
// convert fp32 staging -> fp16 swizzled tile (thread reads exactly the chunks
// it later overwrites via cp.async, so no extra barrier is needed between
// this read and that thread's own subsequent cp.async issue)
__device__ __forceinline__ void cvt_stage(uint32_t sb, int tid) {
#pragma unroll
    for (int it = 0; it < 8; it++) {
        int g = tid + 256 * it;
        int r = g >> 5, c = (g & 31) << 2;
        float4 v;
        LDS128F(v, sb + SM_E32 + (uint32_t)g * 16u);
        __half2 h0 = __float22half2_rn(make_float2(v.x, v.y));
        __half2 h1 = __float22half2_rn(make_float2(v.z, v.w));
        STS64(sb + SM_E16 + swz(r, (uint32_t)c * 2u),
              *(uint32_t*)&h0, *(uint32_t*)&h1);
    }
}

// ============================================================================
// Kernel 2: fp16 mma.sync edge GEMM.
//  - W fragments cached in REGISTERS for the whole kernel (tile-invariant)
//  - e tile: cp.async -> fp32 staging smem -> cvt -> fp16 smem
//  - K tile: cp.async -> padded smem, read in epilogue via conflict-free LDS
// 256 threads, 2 CTAs/SM. Tile = 64 j x 128 d, K=128.
// ============================================================================
__global__ void __launch_bounds__(256, 2)
edge_kernel(const float* __restrict__ e, float* __restrict__ out_e) {
    extern __shared__ char smem[];
    const uint32_t sb = smem_u32(smem);
    const int tid = threadIdx.x, warp = tid >> 5, lane = tid & 31;
    const int m0 = (warp >> 2) * 32;               // 0 or 32
    const int n0 = (warp & 3) * 32;                // 0..96

    // ---- stage W fp16 into SM_E32 (temporarily), swizzled -------------------
#pragma unroll
    for (int it = 0; it < 16; it++) {
        int g = tid + 256 * it;
        int r = g >> 5, c = (g & 31) << 2;
        uint2 a = *(const uint2*)(g_W0T + r * C_ + c);
        STS64(sb + SM_E32 + swz(r, (uint32_t)c * 2u), a.x, a.y);
    }
    __syncthreads();

    // ---- load W fragments into registers (held for the whole kernel) --------
    uint32_t bw[8][2][4];
#pragma unroll
    for (int ks = 0; ks < 8; ks++)
#pragma unroll
        for (int ntp = 0; ntp < 2; ntp++) {
            int drow = n0 + ntp * 16 + ((lane >> 4) << 3) + (lane & 7);
            uint32_t bo = swz(drow, (uint32_t)ks * 32u + (((uint32_t)lane >> 3) & 1u) * 16u);
            LDSM_X4(bw[ks][ntp][0], bw[ks][ntp][1], bw[ks][ntp][2], bw[ks][ntp][3],
                    sb + SM_E32 + bo);
        }
    __syncthreads();

    // ---- prologue: e(0)+K(0), then cvt e(0), then issue e(1) -----------------
    int t = blockIdx.x;
    cp_e_tile(sb, e, t, tid);
    cp_k_tile(sb, t, tid);
    CP_COMMIT();
    CP_WAIT0();
    __syncthreads();
    cvt_stage(sb, tid);
    if (t + GRID_EDGE < NT_) cp_e_tile(sb, e, t + GRID_EDGE, tid);
    CP_COMMIT();
    __syncthreads();

    for (; t < NT_; t += GRID_EDGE) {
        const int bi = t >> 3, j0 = (t & 7) << 6;
        const int b = bi >> 9, i = bi & (N_ - 1);
        const size_t row_base = (size_t)bi * N_ + j0;

        // ---- MMA mainloop (A from sE16, W from registers) -------------------
        float acc[2][4][4];
#pragma unroll
        for (int mt = 0; mt < 2; mt++)
#pragma unroll
            for (int nt = 0; nt < 4; nt++)
#pragma unroll
                for (int k = 0; k < 4; k++) acc[mt][nt][k] = 0.f;

#pragma unroll
        for (int ks = 0; ks < 8; ks++) {
            uint32_t a0[2][4];
#pragma unroll
            for (int mt = 0; mt < 2; mt++) {
                int arow = m0 + mt * 16 + (lane & 15);
                uint32_t ao = swz(arow, (uint32_t)ks * 32u + ((uint32_t)(lane >> 4)) * 16u);
                LDSM_X4(a0[mt][0], a0[mt][1], a0[mt][2], a0[mt][3], sb + SM_E16 + ao);
            }
#pragma unroll
            for (int mt = 0; mt < 2; mt++)
#pragma unroll
                for (int nt = 0; nt < 4; nt++)
                    MMA16816(acc[mt][nt], a0[mt][0], a0[mt][1], a0[mt][2], a0[mt][3],
                             bw[ks][nt >> 1][(nt & 1) * 2], bw[ks][nt >> 1][(nt & 1) * 2 + 1]);
        }

        // ---- wait for K(t) (+ e(t+1)) and make them CTA-visible -------------
        CP_WAIT0();
        __syncthreads();

        // ---- epilogue: gate with Q (gmem) and K (smem), store e_out + g_S ---
        const float* qrow = g_Q + (size_t)bi * C_;
#pragma unroll
        for (int mt = 0; mt < 2; mt++) {
            const int r0 = m0 + mt * 16 + (lane >> 2);   // tile-local j
            const int r1 = r0 + 8;
            float* orow0 = out_e + (row_base + r0) * C_;
            float* orow1 = out_e + (row_base + r1) * C_;
            float hs0 = 0.f, hs1 = 0.f;
#pragma unroll
            for (int nt = 0; nt < 4; nt++) {
                int colp = n0 + nt * 8 + 2 * (lane & 3);
                float2 q2 = *(const float2*)(qrow + colp);
                float2 k0, k1;
                LDS64F(k0, sb + SM_K + (uint32_t)(r0 * 528 + colp * 4));
                LDS64F(k1, sb + SM_K + (uint32_t)(r1 * 528 + colp * 4));
                float2 e0, e1;
                e0.x = acc[mt][nt][0] * q2.x * k0.x;  e0.y = acc[mt][nt][1] * q2.y * k0.y;
                e1.x = acc[mt][nt][2] * q2.x * k1.x;  e1.y = acc[mt][nt][3] * q2.y * k1.y;
                *(float2*)(orow0 + colp) = e0;
                *(float2*)(orow1 + colp) = e1;
                hs0 += e0.x + e0.y;
                hs1 += e1.x + e1.y;
                if (nt & 1) {                        // head complete (2 n-tiles)
                    hs0 += __shfl_xor_sync(0xffffffffu, hs0, 1);
                    hs0 += __shfl_xor_sync(0xffffffffu, hs0, 2);
                    hs1 += __shfl_xor_sync(0xffffffffu, hs1, 1);
                    hs1 += __shfl_xor_sync(0xffffffffu, hs1, 2);
                    if ((lane & 3) == 0) {
                        int head = (n0 >> 4) + (nt >> 1);
                        float c0 = __expf(fminf(fmaxf(hs0, -5.f), 5.f));
                        float c1 = __expf(fminf(fmaxf(hs1, -5.f), 5.f));
                        float* sp = g_S + ((size_t)(b * H_ + head) * N_ + i) * N_ + j0;
                        sp[r0] = c0;
                        sp[r1] = c1;
                    }
                    hs0 = 0.f; hs1 = 0.f;
                }
            }
        }
        __syncthreads();   // everyone done reading sE16(t) and sK(t)

        // ---- cvt e(t+1) into sE16; issue K(t+1) and e(t+2) ------------------
        if (t + GRID_EDGE < NT_) {
            cvt_stage(sb, tid);
            cp_k_tile(sb, t + GRID_EDGE, tid);
            if (t + 2 * GRID_EDGE < NT_) cp_e_tile(sb, e, t + 2 * GRID_EDGE, tid);
            CP_COMMIT();
        }
        __syncthreads();
    }
}

// ============================================================================
// Kernel 3: column-sum partials of exp'ed g_S. float4 loads, deep MLP.
// ============================================================================
__global__ void colsum_kernel() {
    int bh = blockIdx.x & 15, ch = blockIdx.x >> 4;
    int j4 = threadIdx.x;                          // 128 threads
    const float4* base = (const float4*)(g_S + (size_t)bh * N_ * N_
                                         + (size_t)(ch * 16) * N_) + j4;
    float4 acc = make_float4(0.f, 0.f, 0.f, 0.f);
#pragma unroll 16
    for (int ii = 0; ii < 16; ii++) {
        float4 v = __ldg(base + (size_t)ii * (N_ / 4));
        acc.x += v.x; acc.y += v.y; acc.z += v.z; acc.w += v.w;
    }
    *(float4*)(g_cs + (size_t)(ch * 16 + bh) * N_ + 4 * j4) = acc;
}

// ============================================================================
// Kernel 4: h_out fused with softmax normalization.
// ============================================================================
__global__ void __launch_bounds__(256)
hout_kernel(float* __restrict__ out_h) {
    __shared__ float sV[N_ * 16];                  // 32 KB
    __shared__ float sInv[N_];
    int bh = blockIdx.x >> 5, i0 = (blockIdx.x & 31) << 4;
    int b = bh >> 3, head = bh & 7;
    int tid = threadIdx.x, ti = tid >> 4, c = tid & 15;

    for (int it = 0; it < 32; it++) {
        int q = tid + 256 * it;                    // 8192 floats
        int j = q >> 4, cc = q & 15;
        sV[q] = __ldg(g_V + ((size_t)b * N_ + j) * C_ + head * 16 + cc);
    }
    for (int tt = 0; tt < 2; tt++) {
        int j = tid + 256 * tt;
        float s = 0.f;
#pragma unroll
        for (int ch = 0; ch < 32; ch++) s += g_cs[(size_t)(ch * 16 + bh) * N_ + j];
        sInv[j] = 1.f / s;
    }
    __syncthreads();

    int i = i0 + ti;
    const float4* prow = (const float4*)(g_S + ((size_t)bh * N_ + i) * N_);
    float acc = 0.f;
#pragma unroll 4
    for (int j4 = 0; j4 < 128; j4++) {
        float4 p = __ldg(prow + j4);
        int j = 4 * j4;
        acc += p.x * sInv[j]     * sV[(j)     * 16 + c];
        acc += p.y * sInv[j + 1] * sV[(j + 1) * 16 + c];
        acc += p.z * sInv[j + 2] * sV[(j + 2) * 16 + c];
        acc += p.w * sInv[j + 3] * sV[(j + 3) * 16 + c];
    }
    out_h[((size_t)b * N_ + i) * C_ + head * 16 + c] = acc;
}

// ============================================================================
extern "C" void kernel_launch(void* const* d_in, const int* in_sizes, int n_in,
                              void* d_out, int out_size) {
    const float* h  = (const float*)d_in[0];
    const float* e  = (const float*)d_in[1];
    const float* Wq = (const float*)d_in[2];
    const float* Wk = (const float*)d_in[3];
    const float* Wv = (const float*)d_in[4];
    const float* We = (const float*)d_in[5];

    float* out_h = (float*)d_out;                      // [B,N,C]
    float* out_e = (float*)d_out + B_ * N_ * C_;       // [B,N,N,C]

    cudaFuncSetAttribute(edge_kernel,
                         cudaFuncAttributeMaxDynamicSharedMemorySize, SM_TOT);

    prep_w_kernel<<<64, 256>>>(We);
    qkv_kernel<<<384, 256>>>(h, Wq, Wk, Wv);
    edge_kernel<<<GRID_EDGE, 256, SM_TOT>>>(e, out_e);
    colsum_kernel<<<512, 128>>>();
    hout_kernel<<<16 * 32, 256>>>(out_h);
}

// round 14
// speedup vs baseline: 2.6537x; 1.0008x over previous
#include <cuda_runtime.h>
#include <cuda_fp16.h>
#include <cstdint>

#define B_  2
#define N_  512
#define C_  128
#define H_  8
#define NT_ (B_ * N_ * 8)          // 8192 tiles (64 rows each)
#define GRID_EDGE 296

// ---------------- scratch (device globals) ----------------------------------
__device__ float g_Q[B_ * N_ * C_];               // pre-scaled by 0.25
__device__ float g_K[B_ * N_ * C_];
__device__ float g_V[B_ * N_ * C_];
__device__ float g_S[B_ * H_ * N_ * N_];          // [b,h,i,j]; holds exp(clamp(s))
__device__ float g_cs[32 * 16 * N_];              // colsum partials [chunk][bh][j]
__device__ __half g_W0T[C_ * C_];                 // WeT fp16 [d][c]

// ---------------- helpers ----------------------------------------------------
__device__ __forceinline__ uint32_t smem_u32(const void* p) {
    uint32_t a;
    asm("{ .reg .u64 t; cvta.to.shared.u64 t, %1; cvt.u32.u64 %0, t; }" : "=r"(a) : "l"(p));
    return a;
}
#define LDSM_X4(r0, r1, r2, r3, a) \
    asm volatile("ldmatrix.sync.aligned.m8n8.x4.shared.b16 {%0,%1,%2,%3}, [%4];" \
                 : "=r"(r0), "=r"(r1), "=r"(r2), "=r"(r3) : "r"(a))
#define MMA16816(c, a0, a1, a2, a3, b0, b1) \
    asm volatile("mma.sync.aligned.m16n8k16.row.col.f32.f16.f16.f32 " \
                 "{%0,%1,%2,%3}, {%4,%5,%6,%7}, {%8,%9}, {%0,%1,%2,%3};" \
                 : "+f"((c)[0]), "+f"((c)[1]), "+f"((c)[2]), "+f"((c)[3]) \
                 : "r"(a0), "r"(a1), "r"(a2), "r"(a3), "r"(b0), "r"(b1))
#define STS64(a, u0, u1) \
    asm volatile("st.shared.v2.u32 [%0], {%1, %2};" :: "r"(a), "r"(u0), "r"(u1) : "memory")
#define LDS128F(v, a) \
    asm volatile("ld.shared.v4.f32 {%0,%1,%2,%3}, [%4];" \
                 : "=f"((v).x), "=f"((v).y), "=f"((v).z), "=f"((v).w) : "r"(a))
#define LDS64F(v, a) \
    asm volatile("ld.shared.v2.f32 {%0,%1}, [%2];" : "=f"((v).x), "=f"((v).y) : "r"(a))
#define CP_ASYNC16(s, g) \
    asm volatile("cp.async.cg.shared.global [%0], [%1], 16;" :: "r"(s), "l"(g) : "memory")
#define CP_COMMIT()  asm volatile("cp.async.commit_group;" ::: "memory")
#define CP_WAIT0()   asm volatile("cp.async.wait_group 0;" ::: "memory")

// XOR swizzle on 16B chunks within a 256B row (bits 4..6)
__device__ __forceinline__ uint32_t swz(int row, uint32_t cb) {
    return (uint32_t)row * 256u + (cb ^ (((uint32_t)row & 7u) << 4));
}

// dynamic smem byte offsets
#define SM_E16  0u                 // 64x128 fp16 swizzled (16 KB)
#define SM_E32  16384u             // fp32 e staging / initial W staging (32 KB)
#define SM_K    49152u             // 64 rows x 132 floats padded (33792 B)
#define SM_TOT  83968u             // ~82 KB -> 2 CTAs/SM

// ============================================================================
// Kernel 0: transpose + fp16 We -> g_W0T [d][c]
// ============================================================================
__global__ void prep_w_kernel(const float* __restrict__ We) {
    int idx = blockIdx.x * 256 + threadIdx.x;      // [0, 16384)
    int d = idx >> 7, c = idx & 127;
    g_W0T[idx] = __float2half_rn(__ldg(We + c * C_ + d));
}

// ============================================================================
// Kernel 1: Q/K/V projections (Q pre-scaled by 0.25)
// ============================================================================
__global__ void qkv_kernel(const float* __restrict__ h, const float* __restrict__ Wq,
                           const float* __restrict__ Wk, const float* __restrict__ Wv) {
    int gid = blockIdx.x * blockDim.x + threadIdx.x;   // [0, 98304)
    int row = gid / 96, q = gid % 96;
    int mat = q >> 5, d = (q & 31) * 4;
    const float* W   = (mat == 0) ? Wq : (mat == 1) ? Wk : Wv;
    float*       out = (mat == 0) ? g_Q : (mat == 1) ? g_K : g_V;
    const float* hrow = h + (size_t)row * C_;
    float4 acc = make_float4(0.f, 0.f, 0.f, 0.f);
#pragma unroll 4
    for (int c = 0; c < C_; c++) {
        float  hv = __ldg(hrow + c);
        float4 w  = *(const float4*)(W + (size_t)c * C_ + d);
        acc.x += hv * w.x; acc.y += hv * w.y; acc.z += hv * w.z; acc.w += hv * w.w;
    }
    if (mat == 0) { acc.x *= .25f; acc.y *= .25f; acc.z *= .25f; acc.w *= .25f; }
    *(float4*)(out + (size_t)row * C_ + d) = acc;
}

// ============================================================================
// Kernel 2 helpers
// ============================================================================
__device__ __forceinline__ void cp_e_tile(uint32_t sb, const float* e, int t, int tid) {
    const float4* esrc = (const float4*)e
        + ((size_t)(t >> 3) * N_ + ((t & 7) << 6)) * 32;
#pragma unroll
    for (int it = 0; it < 8; it++) {
        int g = tid + 256 * it;
        CP_ASYNC16(sb + SM_E32 + (uint32_t)g * 16u, (const void*)(esrc + g));
    }
}
__device__ __forceinline__ void cp_k_tile(uint32_t sb, int t, int tid) {
    int bi = t >> 3, j0 = (t & 7) << 6, b = bi >> 9;
    const float4* ksrc = (const float4*)(g_K + ((size_t)b * N_ + j0) * C_);
#pragma unroll
    for (int it = 0; it < 8; it++) {
        int g = tid + 256 * it;
        int r = g >> 5, m = g & 31;
        CP_ASYNC16(sb + SM_K + (uint32_t)(r * 528 + m * 16), (const void*)(ksrc + g));
    }
}
// convert fp32 staging -> fp16 swizzled tile (thread reads exactly the chunks
// it later overwrites via cp.async, so no extra barrier is needed between
// this read and that thread's own subsequent cp.async issue)
__device__ __forceinline__ void cvt_stage(uint32_t sb, int tid) {
#pragma unroll
    for (int it = 0; it < 8; it++) {
        int g = tid + 256 * it;
        int r = g >> 5, c = (g & 31) << 2;
        float4 v;
        LDS128F(v, sb + SM_E32 + (uint32_t)g * 16u);
        __half2 h0 = __float22half2_rn(make_float2(v.x, v.y));
        __half2 h1 = __float22half2_rn(make_float2(v.z, v.w));
        STS64(sb + SM_E16 + swz(r, (uint32_t)c * 2u),
              *(uint32_t*)&h0, *(uint32_t*)&h1);
    }
}

// ============================================================================
// Kernel 2: fp16 mma.sync edge GEMM.
//  - W fragments cached in REGISTERS for the whole kernel (tile-invariant)
//  - e tile: cp.async -> fp32 staging smem -> cvt -> fp16 smem
//  - K tile: cp.async -> padded smem, read in epilogue via conflict-free LDS
// 256 threads, 2 CTAs/SM. Tile = 64 j x 128 d, K=128.
// ============================================================================
__global__ void __launch_bounds__(256, 2)
edge_kernel(const float* __restrict__ e, float* __restrict__ out_e) {
    extern __shared__ char smem[];
    const uint32_t sb = smem_u32(smem);
    const int tid = threadIdx.x, warp = tid >> 5, lane = tid & 31;
    const int m0 = (warp >> 2) * 32;               // 0 or 32
    const int n0 = (warp & 3) * 32;                // 0..96

    // ---- stage W fp16 into SM_E32 (temporarily), swizzled -------------------
#pragma unroll
    for (int it = 0; it < 16; it++) {
        int g = tid + 256 * it;
        int r = g >> 5, c = (g & 31) << 2;
        uint2 a = *(const uint2*)(g_W0T + r * C_ + c);
        STS64(sb + SM_E32 + swz(r, (uint32_t)c * 2u), a.x, a.y);
    }
    __syncthreads();

    // ---- load W fragments into registers (held for the whole kernel) --------
    uint32_t bw[8][2][4];
#pragma unroll
    for (int ks = 0; ks < 8; ks++)
#pragma unroll
        for (int ntp = 0; ntp < 2; ntp++) {
            int drow = n0 + ntp * 16 + ((lane >> 4) << 3) + (lane & 7);
            uint32_t bo = swz(drow, (uint32_t)ks * 32u + (((uint32_t)lane >> 3) & 1u) * 16u);
            LDSM_X4(bw[ks][ntp][0], bw[ks][ntp][1], bw[ks][ntp][2], bw[ks][ntp][3],
                    sb + SM_E32 + bo);
        }
    __syncthreads();

    // ---- prologue: e(0)+K(0), then cvt e(0), then issue e(1) -----------------
    int t = blockIdx.x;
    cp_e_tile(sb, e, t, tid);
    cp_k_tile(sb, t, tid);
    CP_COMMIT();
    CP_WAIT0();
    __syncthreads();
    cvt_stage(sb, tid);
    if (t + GRID_EDGE < NT_) cp_e_tile(sb, e, t + GRID_EDGE, tid);
    CP_COMMIT();
    __syncthreads();

    for (; t < NT_; t += GRID_EDGE) {
        const int bi = t >> 3, j0 = (t & 7) << 6;
        const int b = bi >> 9, i = bi & (N_ - 1);
        const size_t row_base = (size_t)bi * N_ + j0;

        // ---- MMA mainloop (A from sE16, W from registers) -------------------
        float acc[2][4][4];
#pragma unroll
        for (int mt = 0; mt < 2; mt++)
#pragma unroll
            for (int nt = 0; nt < 4; nt++)
#pragma unroll
                for (int k = 0; k < 4; k++) acc[mt][nt][k] = 0.f;

#pragma unroll
        for (int ks = 0; ks < 8; ks++) {
            uint32_t a0[2][4];
#pragma unroll
            for (int mt = 0; mt < 2; mt++) {
                int arow = m0 + mt * 16 + (lane & 15);
                uint32_t ao = swz(arow, (uint32_t)ks * 32u + ((uint32_t)(lane >> 4)) * 16u);
                LDSM_X4(a0[mt][0], a0[mt][1], a0[mt][2], a0[mt][3], sb + SM_E16 + ao);
            }
#pragma unroll
            for (int mt = 0; mt < 2; mt++)
#pragma unroll
                for (int nt = 0; nt < 4; nt++)
                    MMA16816(acc[mt][nt], a0[mt][0], a0[mt][1], a0[mt][2], a0[mt][3],
                             bw[ks][nt >> 1][(nt & 1) * 2], bw[ks][nt >> 1][(nt & 1) * 2 + 1]);
        }

        // ---- wait for K(t) (+ e(t+1)) and make them CTA-visible -------------
        CP_WAIT0();
        __syncthreads();

        // ---- epilogue: gate with Q (gmem) and K (smem), store e_out + g_S ---
        const float* qrow = g_Q + (size_t)bi * C_;
#pragma unroll
        for (int mt = 0; mt < 2; mt++) {
            const int r0 = m0 + mt * 16 + (lane >> 2);   // tile-local j
            const int r1 = r0 + 8;
            float* orow0 = out_e + (row_base + r0) * C_;
            float* orow1 = out_e + (row_base + r1) * C_;
            float hs0 = 0.f, hs1 = 0.f;
#pragma unroll
            for (int nt = 0; nt < 4; nt++) {
                int colp = n0 + nt * 8 + 2 * (lane & 3);
                float2 q2 = *(const float2*)(qrow + colp);
                float2 k0, k1;
                LDS64F(k0, sb + SM_K + (uint32_t)(r0 * 528 + colp * 4));
                LDS64F(k1, sb + SM_K + (uint32_t)(r1 * 528 + colp * 4));
                float2 e0, e1;
                e0.x = acc[mt][nt][0] * q2.x * k0.x;  e0.y = acc[mt][nt][1] * q2.y * k0.y;
                e1.x = acc[mt][nt][2] * q2.x * k1.x;  e1.y = acc[mt][nt][3] * q2.y * k1.y;
                *(float2*)(orow0 + colp) = e0;
                *(float2*)(orow1 + colp) = e1;
                hs0 += e0.x + e0.y;
                hs1 += e1.x + e1.y;
                if (nt & 1) {                        // head complete (2 n-tiles)
                    hs0 += __shfl_xor_sync(0xffffffffu, hs0, 1);
                    hs0 += __shfl_xor_sync(0xffffffffu, hs0, 2);
                    hs1 += __shfl_xor_sync(0xffffffffu, hs1, 1);
                    hs1 += __shfl_xor_sync(0xffffffffu, hs1, 2);
                    if ((lane & 3) == 0) {
                        int head = (n0 >> 4) + (nt >> 1);
                        float c0 = __expf(fminf(fmaxf(hs0, -5.f), 5.f));
                        float c1 = __expf(fminf(fmaxf(hs1, -5.f), 5.f));
                        float* sp = g_S + ((size_t)(b * H_ + head) * N_ + i) * N_ + j0;
                        sp[r0] = c0;
                        sp[r1] = c1;
                    }
                    hs0 = 0.f; hs1 = 0.f;
                }
            }
        }
        __syncthreads();   // everyone done reading sE16(t) and sK(t)

        // ---- cvt e(t+1) into sE16; issue K(t+1) and e(t+2) ------------------
        if (t + GRID_EDGE < NT_) {
            cvt_stage(sb, tid);
            cp_k_tile(sb, t + GRID_EDGE, tid);
            if (t + 2 * GRID_EDGE < NT_) cp_e_tile(sb, e, t + 2 * GRID_EDGE, tid);
            CP_COMMIT();
        }
        __syncthreads();
    }
}

// ============================================================================
// Kernel 3: column-sum partials of exp'ed g_S. float4 loads, deep MLP.
// ============================================================================
__global__ void colsum_kernel() {
    int bh = blockIdx.x & 15, ch = blockIdx.x >> 4;
    int j4 = threadIdx.x;                          // 128 threads
    const float4* base = (const float4*)(g_S + (size_t)bh * N_ * N_
                                         + (size_t)(ch * 16) * N_) + j4;
    float4 acc = make_float4(0.f, 0.f, 0.f, 0.f);
#pragma unroll 16
    for (int ii = 0; ii < 16; ii++) {
        float4 v = __ldg(base + (size_t)ii * (N_ / 4));
        acc.x += v.x; acc.y += v.y; acc.z += v.z; acc.w += v.w;
    }
    *(float4*)(g_cs + (size_t)(ch * 16 + bh) * N_ + 4 * j4) = acc;
}

// ============================================================================
// Kernel 4: h_out fused with softmax normalization.
// ============================================================================
__global__ void __launch_bounds__(256)
hout_kernel(float* __restrict__ out_h) {
    __shared__ float sV[N_ * 16];                  // 32 KB
    __shared__ float sInv[N_];
    int bh = blockIdx.x >> 5, i0 = (blockIdx.x & 31) << 4;
    int b = bh >> 3, head = bh & 7;
    int tid = threadIdx.x, ti = tid >> 4, c = tid & 15;

    for (int it = 0; it < 32; it++) {
        int q = tid + 256 * it;                    // 8192 floats
        int j = q >> 4, cc = q & 15;
        sV[q] = __ldg(g_V + ((size_t)b * N_ + j) * C_ + head * 16 + cc);
    }
    for (int tt = 0; tt < 2; tt++) {
        int j = tid + 256 * tt;
        float s = 0.f;
#pragma unroll
        for (int ch = 0; ch < 32; ch++) s += g_cs[(size_t)(ch * 16 + bh) * N_ + j];
        sInv[j] = 1.f / s;
    }
    __syncthreads();

    int i = i0 + ti;
    const float4* prow = (const float4*)(g_S + ((size_t)bh * N_ + i) * N_);
    float acc = 0.f;
#pragma unroll 4
    for (int j4 = 0; j4 < 128; j4++) {
        float4 p = __ldg(prow + j4);
        int j = 4 * j4;
        acc += p.x * sInv[j]     * sV[(j)     * 16 + c];
        acc += p.y * sInv[j + 1] * sV[(j + 1) * 16 + c];
        acc += p.z * sInv[j + 2] * sV[(j + 2) * 16 + c];
        acc += p.w * sInv[j + 3] * sV[(j + 3) * 16 + c];
    }
    out_h[((size_t)b * N_ + i) * C_ + head * 16 + c] = acc;
}

// ============================================================================
extern "C" void kernel_launch(void* const* d_in, const int* in_sizes, int n_in,
                              void* d_out, int out_size) {
    const float* h  = (const float*)d_in[0];
    const float* e  = (const float*)d_in[1];
    const float* Wq = (const float*)d_in[2];
    const float* Wk = (const float*)d_in[3];
    const float* Wv = (const float*)d_in[4];
    const float* We = (const float*)d_in[5];

    float* out_h = (float*)d_out;                      // [B,N,C]
    float* out_e = (float*)d_out + B_ * N_ * C_;       // [B,N,N,C]

    cudaFuncSetAttribute(edge_kernel,
                         cudaFuncAttributeMaxDynamicSharedMemorySize, SM_TOT);

    prep_w_kernel<<<64, 256>>>(We);
    qkv_kernel<<<384, 256>>>(h, Wq, Wk, Wv);
    edge_kernel<<<GRID_EDGE, 256, SM_TOT>>>(e, out_e);
    colsum_kernel<<<512, 128>>>();
    hout_kernel<<<16 * 32, 256>>>(out_h);
}

// round 15
// speedup vs baseline: 2.9715x; 1.1198x over previous
#include <cuda_runtime.h>
#include <cuda_fp16.h>
#include <cstdint>

#define B_  2
#define N_  512
#define C_  128
#define H_  8
#define STRIDE_I 18                // CTAs per stripe; grid = 16*18 = 288

// ---------------- scratch (device globals) ----------------------------------
__device__ float g_Q[B_ * N_ * C_];               // pre-scaled by 0.25
__device__ float g_K[B_ * N_ * C_];
__device__ float g_V[B_ * N_ * C_];
__device__ float g_S[B_ * H_ * N_ * N_];          // [b,h,i,j]; holds exp(clamp(s))
__device__ float g_cs[32 * 16 * N_];              // colsum partials [chunk][bh][j]
__device__ __half g_W0T[C_ * C_];                 // WeT fp16 [d][c]

// ---------------- helpers ----------------------------------------------------
__device__ __forceinline__ uint32_t smem_u32(const void* p) {
    uint32_t a;
    asm("{ .reg .u64 t; cvta.to.shared.u64 t, %1; cvt.u32.u64 %0, t; }" : "=r"(a) : "l"(p));
    return a;
}
#define LDSM_X4(r0, r1, r2, r3, a) \
    asm volatile("ldmatrix.sync.aligned.m8n8.x4.shared.b16 {%0,%1,%2,%3}, [%4];" \
                 : "=r"(r0), "=r"(r1), "=r"(r2), "=r"(r3) : "r"(a))
#define MMA16816(c, a0, a1, a2, a3, b0, b1) \
    asm volatile("mma.sync.aligned.m16n8k16.row.col.f32.f16.f16.f32 " \
                 "{%0,%1,%2,%3}, {%4,%5,%6,%7}, {%8,%9}, {%0,%1,%2,%3};" \
                 : "+f"((c)[0]), "+f"((c)[1]), "+f"((c)[2]), "+f"((c)[3]) \
                 : "r"(a0), "r"(a1), "r"(a2), "r"(a3), "r"(b0), "r"(b1))
#define STS64(a, u0, u1) \
    asm volatile("st.shared.v2.u32 [%0], {%1, %2};" :: "r"(a), "r"(u0), "r"(u1) : "memory")
#define LDS128F(v, a) \
    asm volatile("ld.shared.v4.f32 {%0,%1,%2,%3}, [%4];" \
                 : "=f"((v).x), "=f"((v).y), "=f"((v).z), "=f"((v).w) : "r"(a))
#define LDS64F(v, a) \
    asm volatile("ld.shared.v2.f32 {%0,%1}, [%2];" : "=f"((v).x), "=f"((v).y) : "r"(a))
#define CP_ASYNC16(s, g) \
    asm volatile("cp.async.cg.shared.global [%0], [%1], 16;" :: "r"(s), "l"(g) : "memory")
#define CP_COMMIT()  asm volatile("cp.async.commit_group;" ::: "memory")
#define CP_WAIT0()   asm volatile("cp.async.wait_group 0;" ::: "memory")

// XOR swizzle on 16B chunks within a 256B row (bits 4..6)
__device__ __forceinline__ uint32_t swz(int row, uint32_t cb) {
    return (uint32_t)row * 256u + (cb ^ (((uint32_t)row & 7u) << 4));
}

// dynamic smem byte offsets
#define SM_E16A 0u                 // 64x128 fp16 swizzled (16 KB)
#define SM_E16B 16384u             // second fp16 buffer (16 KB)
#define SM_E32  32768u             // fp32 e staging / initial W staging (32 KB)
#define SM_K    65536u             // 64 rows x 132 floats padded (33792 B)
#define SM_TOT  99328u             // ~97 KB -> 2 CTAs/SM

// ============================================================================
// Kernel 0: transpose + fp16 We -> g_W0T [d][c]
// ============================================================================
__global__ void prep_w_kernel(const float* __restrict__ We) {
    int idx = blockIdx.x * 256 + threadIdx.x;      // [0, 16384)
    int d = idx >> 7, c = idx & 127;
    g_W0T[idx] = __float2half_rn(__ldg(We + c * C_ + d));
}

// ============================================================================
// Kernel 1: Q/K/V projections (Q pre-scaled by 0.25)
// ============================================================================
__global__ void qkv_kernel(const float* __restrict__ h, const float* __restrict__ Wq,
                           const float* __restrict__ Wk, const float* __restrict__ Wv) {
    int gid = blockIdx.x * blockDim.x + threadIdx.x;   // [0, 98304)
    int row = gid / 96, q = gid % 96;
    int mat = q >> 5, d = (q & 31) * 4;
    const float* W   = (mat == 0) ? Wq : (mat == 1) ? Wk : Wv;
    float*       out = (mat == 0) ? g_Q : (mat == 1) ? g_K : g_V;
    const float* hrow = h + (size_t)row * C_;
    float4 acc = make_float4(0.f, 0.f, 0.f, 0.f);
#pragma unroll 4
    for (int c = 0; c < C_; c++) {
        float  hv = __ldg(hrow + c);
        float4 w  = *(const float4*)(W + (size_t)c * C_ + d);
        acc.x += hv * w.x; acc.y += hv * w.y; acc.z += hv * w.z; acc.w += hv * w.w;
    }
    if (mat == 0) { acc.x *= .25f; acc.y *= .25f; acc.z *= .25f; acc.w *= .25f; }
    *(float4*)(out + (size_t)row * C_ + d) = acc;
}

// ============================================================================
// Kernel 2 helpers
// ============================================================================
__device__ __forceinline__ void cp_e_tile(uint32_t sb, const float* e,
                                          int bi, int j0, int tid) {
    const float4* esrc = (const float4*)e + ((size_t)bi * N_ + j0) * 32;
#pragma unroll
    for (int it = 0; it < 8; it++) {
        int g = tid + 256 * it;
        CP_ASYNC16(sb + SM_E32 + (uint32_t)g * 16u, (const void*)(esrc + g));
    }
}
// convert fp32 staging -> fp16 swizzled tile at dst
__device__ __forceinline__ void cvt_stage(uint32_t sb, uint32_t dst, int tid) {
#pragma unroll
    for (int it = 0; it < 8; it++) {
        int g = tid + 256 * it;
        int r = g >> 5, c = (g & 31) << 2;
        float4 v;
        LDS128F(v, sb + SM_E32 + (uint32_t)g * 16u);
        __half2 h0 = __float22half2_rn(make_float2(v.x, v.y));
        __half2 h1 = __float22half2_rn(make_float2(v.z, v.w));
        STS64(dst + swz(r, (uint32_t)c * 2u), *(uint32_t*)&h0, *(uint32_t*)&h1);
    }
}

// ============================================================================
// Kernel 2: fp16 mma.sync edge GEMM, stripe-resident K, 1 barrier per tile.
// Grid = 288 = 16 stripes (b x j0) x 18 CTAs; CTA iterates i with stride 18.
//  - W fragments in registers (whole kernel)
//  - K tile resident in smem (loaded once per CTA)
//  - e: cp.async -> fp32 staging -> cvt -> double-buffered fp16 smem
// ============================================================================
__global__ void __launch_bounds__(256, 2)
edge_kernel(const float* __restrict__ e, float* __restrict__ out_e) {
    extern __shared__ char smem[];
    const uint32_t sb = smem_u32(smem);
    const int tid = threadIdx.x, warp = tid >> 5, lane = tid & 31;
    const int m0 = (warp >> 2) * 32;               // 0 or 32
    const int n0 = (warp & 3) * 32;                // 0..96
    const int stripe = blockIdx.x & 15;            // 16 stripes
    const int w0 = blockIdx.x >> 4;                // 0..17, first i
    const int b = stripe >> 3, j0 = (stripe & 7) << 6;

    // ---- stage W fp16 into SM_E32 (temporarily), swizzled -------------------
#pragma unroll
    for (int it = 0; it < 16; it++) {
        int g = tid + 256 * it;
        int r = g >> 5, c = (g & 31) << 2;
        uint2 a = *(const uint2*)(g_W0T + r * C_ + c);
        STS64(sb + SM_E32 + swz(r, (uint32_t)c * 2u), a.x, a.y);
    }
    __syncthreads();

    // ---- load W fragments into registers (held for the whole kernel) --------
    uint32_t bw[8][2][4];
#pragma unroll
    for (int ks = 0; ks < 8; ks++)
#pragma unroll
        for (int ntp = 0; ntp < 2; ntp++) {
            int drow = n0 + ntp * 16 + ((lane >> 4) << 3) + (lane & 7);
            uint32_t bo = swz(drow, (uint32_t)ks * 32u + (((uint32_t)lane >> 3) & 1u) * 16u);
            LDSM_X4(bw[ks][ntp][0], bw[ks][ntp][1], bw[ks][ntp][2], bw[ks][ntp][3],
                    sb + SM_E32 + bo);
        }
    __syncthreads();

    // ---- prologue: K (once) + e(i=w0); cvt; issue e(w0+18) -------------------
    {
        const float4* ksrc = (const float4*)(g_K + ((size_t)b * N_ + j0) * C_);
#pragma unroll
        for (int it = 0; it < 8; it++) {
            int g = tid + 256 * it;
            int r = g >> 5, m = g & 31;
            CP_ASYNC16(sb + SM_K + (uint32_t)(r * 528 + m * 16), (const void*)(ksrc + g));
        }
    }
    cp_e_tile(sb, e, b * N_ + w0, j0, tid);
    CP_COMMIT();
    CP_WAIT0();
    __syncthreads();                               // K + e(w0) visible CTA-wide
    cvt_stage(sb, SM_E16A + sb, tid);
    if (w0 + STRIDE_I < N_) { cp_e_tile(sb, e, b * N_ + w0 + STRIDE_I, j0, tid); CP_COMMIT(); }
    __syncthreads();                               // E16A visible

    int k = 0;
    for (int i = w0; i < N_; i += STRIDE_I, k++) {
        const int p = k & 1;
        const uint32_t eb = sb + (p ? SM_E16B : SM_E16A);
        const int bi = b * N_ + i;
        const size_t row_base = (size_t)bi * N_ + j0;

        // ---- MMA mainloop (A from eb, W from registers) ---------------------
        float acc[2][4][4];
#pragma unroll
        for (int mt = 0; mt < 2; mt++)
#pragma unroll
            for (int nt = 0; nt < 4; nt++)
#pragma unroll
                for (int kk = 0; kk < 4; kk++) acc[mt][nt][kk] = 0.f;

#pragma unroll
        for (int ks = 0; ks < 8; ks++) {
            uint32_t a0[2][4];
#pragma unroll
            for (int mt = 0; mt < 2; mt++) {
                int arow = m0 + mt * 16 + (lane & 15);
                uint32_t ao = swz(arow, (uint32_t)ks * 32u + ((uint32_t)(lane >> 4)) * 16u);
                LDSM_X4(a0[mt][0], a0[mt][1], a0[mt][2], a0[mt][3], eb + ao);
            }
#pragma unroll
            for (int mt = 0; mt < 2; mt++)
#pragma unroll
                for (int nt = 0; nt < 4; nt++)
                    MMA16816(acc[mt][nt], a0[mt][0], a0[mt][1], a0[mt][2], a0[mt][3],
                             bw[ks][nt >> 1][(nt & 1) * 2], bw[ks][nt >> 1][(nt & 1) * 2 + 1]);
        }

        // ---- epilogue: gate with Q (gmem) and resident K (smem) -------------
        const float* qrow = g_Q + (size_t)bi * C_;
#pragma unroll
        for (int mt = 0; mt < 2; mt++) {
            const int r0 = m0 + mt * 16 + (lane >> 2);   // tile-local j
            const int r1 = r0 + 8;
            float* orow0 = out_e + (row_base + r0) * C_;
            float* orow1 = out_e + (row_base + r1) * C_;
            float hs0 = 0.f, hs1 = 0.f;
#pragma unroll
            for (int nt = 0; nt < 4; nt++) {
                int colp = n0 + nt * 8 + 2 * (lane & 3);
                float2 q2 = *(const float2*)(qrow + colp);
                float2 k0, k1;
                LDS64F(k0, sb + SM_K + (uint32_t)(r0 * 528 + colp * 4));
                LDS64F(k1, sb + SM_K + (uint32_t)(r1 * 528 + colp * 4));
                float2 e0, e1;
                e0.x = acc[mt][nt][0] * q2.x * k0.x;  e0.y = acc[mt][nt][1] * q2.y * k0.y;
                e1.x = acc[mt][nt][2] * q2.x * k1.x;  e1.y = acc[mt][nt][3] * q2.y * k1.y;
                *(float2*)(orow0 + colp) = e0;
                *(float2*)(orow1 + colp) = e1;
                hs0 += e0.x + e0.y;
                hs1 += e1.x + e1.y;
                if (nt & 1) {                        // head complete (2 n-tiles)
                    hs0 += __shfl_xor_sync(0xffffffffu, hs0, 1);
                    hs0 += __shfl_xor_sync(0xffffffffu, hs0, 2);
                    hs1 += __shfl_xor_sync(0xffffffffu, hs1, 1);
                    hs1 += __shfl_xor_sync(0xffffffffu, hs1, 2);
                    if ((lane & 3) == 0) {
                        int head = (n0 >> 4) + (nt >> 1);
                        float c0 = __expf(fminf(fmaxf(hs0, -5.f), 5.f));
                        float c1 = __expf(fminf(fmaxf(hs1, -5.f), 5.f));
                        float* sp = g_S + ((size_t)(b * H_ + head) * N_ + i) * N_ + j0;
                        sp[r0] = c0;
                        sp[r1] = c1;
                    }
                    hs0 = 0.f; hs1 = 0.f;
                }
            }
        }

        // ---- cvt e(i+18) into the other fp16 buffer; issue e(i+36) ----------
        // Per-thread hazards only: each thread cvt-reads exactly the E32
        // chunks it cp.async'd (wait_group 0 orders them), and overwrites
        // E32 only after its own reads (program order).
        if (i + STRIDE_I < N_) {
            CP_WAIT0();
            cvt_stage(sb, sb + (p ? SM_E16A : SM_E16B), tid);
            if (i + 2 * STRIDE_I < N_) {
                cp_e_tile(sb, e, bi + 2 * STRIDE_I, j0, tid);
                CP_COMMIT();
            }
        }
        __syncthreads();   // single barrier: E16[p^1] handoff + tile retire
    }
}

// ============================================================================
// Kernel 3: column-sum partials of exp'ed g_S. float4 loads, deep MLP.
// ============================================================================
__global__ void colsum_kernel() {
    int bh = blockIdx.x & 15, ch = blockIdx.x >> 4;
    int j4 = threadIdx.x;                          // 128 threads
    const float4* base = (const float4*)(g_S + (size_t)bh * N_ * N_
                                         + (size_t)(ch * 16) * N_) + j4;
    float4 acc = make_float4(0.f, 0.f, 0.f, 0.f);
#pragma unroll 16
    for (int ii = 0; ii < 16; ii++) {
        float4 v = __ldg(base + (size_t)ii * (N_ / 4));
        acc.x += v.x; acc.y += v.y; acc.z += v.z; acc.w += v.w;
    }
    *(float4*)(g_cs + (size_t)(ch * 16 + bh) * N_ + 4 * j4) = acc;
}

// ============================================================================
// Kernel 4: h_out fused with softmax normalization.
// ============================================================================
__global__ void __launch_bounds__(256)
hout_kernel(float* __restrict__ out_h) {
    __shared__ float sV[N_ * 16];                  // 32 KB
    __shared__ float sInv[N_];
    int bh = blockIdx.x >> 5, i0 = (blockIdx.x & 31) << 4;
    int b = bh >> 3, head = bh & 7;
    int tid = threadIdx.x, ti = tid >> 4, c = tid & 15;

    for (int it = 0; it < 32; it++) {
        int q = tid + 256 * it;                    // 8192 floats
        int j = q >> 4, cc = q & 15;
        sV[q] = __ldg(g_V + ((size_t)b * N_ + j) * C_ + head * 16 + cc);
    }
    for (int tt = 0; tt < 2; tt++) {
        int j = tid + 256 * tt;
        float s = 0.f;
#pragma unroll
        for (int ch = 0; ch < 32; ch++) s += g_cs[(size_t)(ch * 16 + bh) * N_ + j];
        sInv[j] = 1.f / s;
    }
    __syncthreads();

    int i = i0 + ti;
    const float4* prow = (const float4*)(g_S + ((size_t)bh * N_ + i) * N_);
    float acc = 0.f;
#pragma unroll 4
    for (int j4 = 0; j4 < 128; j4++) {
        float4 p = __ldg(prow + j4);
        int j = 4 * j4;
        acc += p.x * sInv[j]     * sV[(j)     * 16 + c];
        acc += p.y * sInv[j + 1] * sV[(j + 1) * 16 + c];
        acc += p.z * sInv[j + 2] * sV[(j + 2) * 16 + c];
        acc += p.w * sInv[j + 3] * sV[(j + 3) * 16 + c];
    }
    out_h[((size_t)b * N_ + i) * C_ + head * 16 + c] = acc;
}

// ============================================================================
extern "C" void kernel_launch(void* const* d_in, const int* in_sizes, int n_in,
                              void* d_out, int out_size) {
    const float* h  = (const float*)d_in[0];
    const float* e  = (const float*)d_in[1];
    const float* Wq = (const float*)d_in[2];
    const float* Wk = (const float*)d_in[3];
    const float* Wv = (const float*)d_in[4];
    const float* We = (const float*)d_in[5];

    float* out_h = (float*)d_out;                      // [B,N,C]
    float* out_e = (float*)d_out + B_ * N_ * C_;       // [B,N,N,C]

    cudaFuncSetAttribute(edge_kernel,
                         cudaFuncAttributeMaxDynamicSharedMemorySize, SM_TOT);

    prep_w_kernel<<<64, 256>>>(We);
    qkv_kernel<<<384, 256>>>(h, Wq, Wk, Wv);
    edge_kernel<<<16 * STRIDE_I, 256, SM_TOT>>>(e, out_e);
    colsum_kernel<<<512, 128>>>();
    hout_kernel<<<16 * 32, 256>>>(out_h);
}

// round 16
// speedup vs baseline: 3.0433x; 1.0242x over previous
#include <cuda_runtime.h>
#include <cuda_fp16.h>
#include <cstdint>

#define B_  2
#define N_  512
#define C_  128
#define H_  8
#define STRIDE_I 18                // CTAs per stripe; grid = 16*18 = 288

// ---------------- scratch (device globals) ----------------------------------
__device__ float g_Q[B_ * N_ * C_];               // pre-scaled by 0.25
__device__ float g_K[B_ * N_ * C_];
__device__ float g_V[B_ * N_ * C_];
__device__ float g_S[B_ * H_ * N_ * N_];          // [b,h,i,j]; holds exp(clamp(s))
__device__ float g_cs2[STRIDE_I * 16 * N_];       // colsum partials [w0][bh][j]
__device__ __half g_W0T[C_ * C_];                 // WeT fp16 [d][c]

// ---------------- helpers ----------------------------------------------------
__device__ __forceinline__ uint32_t smem_u32(const void* p) {
    uint32_t a;
    asm("{ .reg .u64 t; cvta.to.shared.u64 t, %1; cvt.u32.u64 %0, t; }" : "=r"(a) : "l"(p));
    return a;
}
#define LDSM_X4(r0, r1, r2, r3, a) \
    asm volatile("ldmatrix.sync.aligned.m8n8.x4.shared.b16 {%0,%1,%2,%3}, [%4];" \
                 : "=r"(r0), "=r"(r1), "=r"(r2), "=r"(r3) : "r"(a))
#define MMA16816(c, a0, a1, a2, a3, b0, b1) \
    asm volatile("mma.sync.aligned.m16n8k16.row.col.f32.f16.f16.f32 " \
                 "{%0,%1,%2,%3}, {%4,%5,%6,%7}, {%8,%9}, {%0,%1,%2,%3};" \
                 : "+f"((c)[0]), "+f"((c)[1]), "+f"((c)[2]), "+f"((c)[3]) \
                 : "r"(a0), "r"(a1), "r"(a2), "r"(a3), "r"(b0), "r"(b1))
#define STS64(a, u0, u1) \
    asm volatile("st.shared.v2.u32 [%0], {%1, %2};" :: "r"(a), "r"(u0), "r"(u1) : "memory")
#define LDS128F(v, a) \
    asm volatile("ld.shared.v4.f32 {%0,%1,%2,%3}, [%4];" \
                 : "=f"((v).x), "=f"((v).y), "=f"((v).z), "=f"((v).w) : "r"(a))
#define LDS64F(v, a) \
    asm volatile("ld.shared.v2.f32 {%0,%1}, [%2];" : "=f"((v).x), "=f"((v).y) : "r"(a))
#define CP_ASYNC16(s, g) \
    asm volatile("cp.async.cg.shared.global [%0], [%1], 16;" :: "r"(s), "l"(g) : "memory")
#define CP_COMMIT()  asm volatile("cp.async.commit_group;" ::: "memory")
#define CP_WAIT0()   asm volatile("cp.async.wait_group 0;" ::: "memory")

// XOR swizzle on 16B chunks within a 256B row (bits 4..6)
__device__ __forceinline__ uint32_t swz(int row, uint32_t cb) {
    return (uint32_t)row * 256u + (cb ^ (((uint32_t)row & 7u) << 4));
}

// dynamic smem byte offsets
#define SM_E16A 0u                 // 64x128 fp16 swizzled (16 KB)
#define SM_E16B 16384u             // second fp16 buffer (16 KB)
#define SM_E32  32768u             // fp32 e staging / initial W staging (32 KB)
#define SM_K    65536u             // 64 rows x 132 floats padded (33792 B)
#define SM_TOT  99328u             // ~97 KB -> 2 CTAs/SM

// ============================================================================
// Kernel 0: transpose + fp16 We -> g_W0T [d][c]
// ============================================================================
__global__ void prep_w_kernel(const float* __restrict__ We) {
    int idx = blockIdx.x * 256 + threadIdx.x;      // [0, 16384)
    int d = idx >> 7, c = idx & 127;
    g_W0T[idx] = __float2half_rn(__ldg(We + c * C_ + d));
}

// ============================================================================
// Kernel 1: Q/K/V projections (Q pre-scaled by 0.25)
// ============================================================================
__global__ void qkv_kernel(const float* __restrict__ h, const float* __restrict__ Wq,
                           const float* __restrict__ Wk, const float* __restrict__ Wv) {
    int gid = blockIdx.x * blockDim.x + threadIdx.x;   // [0, 98304)
    int row = gid / 96, q = gid % 96;
    int mat = q >> 5, d = (q & 31) * 4;
    const float* W   = (mat == 0) ? Wq : (mat == 1) ? Wk : Wv;
    float*       out = (mat == 0) ? g_Q : (mat == 1) ? g_K : g_V;
    const float* hrow = h + (size_t)row * C_;
    float4 acc = make_float4(0.f, 0.f, 0.f, 0.f);
#pragma unroll 4
    for (int c = 0; c < C_; c++) {
        float  hv = __ldg(hrow + c);
        float4 w  = *(const float4*)(W + (size_t)c * C_ + d);
        acc.x += hv * w.x; acc.y += hv * w.y; acc.z += hv * w.z; acc.w += hv * w.w;
    }
    if (mat == 0) { acc.x *= .25f; acc.y *= .25f; acc.z *= .25f; acc.w *= .25f; }
    *(float4*)(out + (size_t)row * C_ + d) = acc;
}

// ============================================================================
// Kernel 2 helpers
// ============================================================================
__device__ __forceinline__ void cp_e_tile(uint32_t sb, const float* e,
                                          int bi, int j0, int tid) {
    const float4* esrc = (const float4*)e + ((size_t)bi * N_ + j0) * 32;
#pragma unroll
    for (int it = 0; it < 8; it++) {
        int g = tid + 256 * it;
        CP_ASYNC16(sb + SM_E32 + (uint32_t)g * 16u, (const void*)(esrc + g));
    }
}
// convert fp32 staging -> fp16 swizzled tile at dst
__device__ __forceinline__ void cvt_stage(uint32_t sb, uint32_t dst, int tid) {
#pragma unroll
    for (int it = 0; it < 8; it++) {
        int g = tid + 256 * it;
        int r = g >> 5, c = (g & 31) << 2;
        float4 v;
        LDS128F(v, sb + SM_E32 + (uint32_t)g * 16u);
        __half2 h0 = __float22half2_rn(make_float2(v.x, v.y));
        __half2 h1 = __float22half2_rn(make_float2(v.z, v.w));
        STS64(dst + swz(r, (uint32_t)c * 2u), *(uint32_t*)&h0, *(uint32_t*)&h1);
    }
}

// ============================================================================
// Kernel 2: fp16 mma.sync edge GEMM, stripe-resident K, 1 barrier per tile,
// colsum folded into the epilogue (per-CTA deterministic partials).
// Grid = 288 = 16 stripes (b x j0) x 18 CTAs; CTA iterates i with stride 18.
// ============================================================================
__global__ void __launch_bounds__(256, 2)
edge_kernel(const float* __restrict__ e, float* __restrict__ out_e) {
    extern __shared__ char smem[];
    const uint32_t sb = smem_u32(smem);
    const int tid = threadIdx.x, warp = tid >> 5, lane = tid & 31;
    const int m0 = (warp >> 2) * 32;               // 0 or 32
    const int n0 = (warp & 3) * 32;                // 0..96
    const int stripe = blockIdx.x & 15;            // 16 stripes
    const int w0 = blockIdx.x >> 4;                // 0..17, first i
    const int b = stripe >> 3, j0 = (stripe & 7) << 6;

    // ---- stage W fp16 into SM_E32 (temporarily), swizzled -------------------
#pragma unroll
    for (int it = 0; it < 16; it++) {
        int g = tid + 256 * it;
        int r = g >> 5, c = (g & 31) << 2;
        uint2 a = *(const uint2*)(g_W0T + r * C_ + c);
        STS64(sb + SM_E32 + swz(r, (uint32_t)c * 2u), a.x, a.y);
    }
    __syncthreads();

    // ---- load W fragments into registers (held for the whole kernel) --------
    uint32_t bw[8][2][4];
#pragma unroll
    for (int ks = 0; ks < 8; ks++)
#pragma unroll
        for (int ntp = 0; ntp < 2; ntp++) {
            int drow = n0 + ntp * 16 + ((lane >> 4) << 3) + (lane & 7);
            uint32_t bo = swz(drow, (uint32_t)ks * 32u + (((uint32_t)lane >> 3) & 1u) * 16u);
            LDSM_X4(bw[ks][ntp][0], bw[ks][ntp][1], bw[ks][ntp][2], bw[ks][ntp][3],
                    sb + SM_E32 + bo);
        }
    __syncthreads();

    // ---- prologue: K (once) + e(i=w0); cvt; issue e(w0+18) -------------------
    {
        const float4* ksrc = (const float4*)(g_K + ((size_t)b * N_ + j0) * C_);
#pragma unroll
        for (int it = 0; it < 8; it++) {
            int g = tid + 256 * it;
            int r = g >> 5, m = g & 31;
            CP_ASYNC16(sb + SM_K + (uint32_t)(r * 528 + m * 16), (const void*)(ksrc + g));
        }
    }
    cp_e_tile(sb, e, b * N_ + w0, j0, tid);
    CP_COMMIT();
    CP_WAIT0();
    __syncthreads();                               // K + e(w0) visible CTA-wide
    cvt_stage(sb, SM_E16A + sb, tid);
    if (w0 + STRIDE_I < N_) { cp_e_tile(sb, e, b * N_ + w0 + STRIDE_I, j0, tid); CP_COMMIT(); }
    __syncthreads();                               // E16A visible

    float cs[2][2][2];                             // colsum partials [mt][ntg][r0/r1]
#pragma unroll
    for (int a = 0; a < 2; a++)
#pragma unroll
        for (int bb = 0; bb < 2; bb++) { cs[a][bb][0] = 0.f; cs[a][bb][1] = 0.f; }

    int k = 0;
    for (int i = w0; i < N_; i += STRIDE_I, k++) {
        const int p = k & 1;
        const uint32_t eb = sb + (p ? SM_E16B : SM_E16A);
        const int bi = b * N_ + i;
        const size_t row_base = (size_t)bi * N_ + j0;

        // ---- MMA mainloop (A from eb, W from registers) ---------------------
        float acc[2][4][4];
#pragma unroll
        for (int mt = 0; mt < 2; mt++)
#pragma unroll
            for (int nt = 0; nt < 4; nt++)
#pragma unroll
                for (int kk = 0; kk < 4; kk++) acc[mt][nt][kk] = 0.f;

#pragma unroll
        for (int ks = 0; ks < 8; ks++) {
            uint32_t a0[2][4];
#pragma unroll
            for (int mt = 0; mt < 2; mt++) {
                int arow = m0 + mt * 16 + (lane & 15);
                uint32_t ao = swz(arow, (uint32_t)ks * 32u + ((uint32_t)(lane >> 4)) * 16u);
                LDSM_X4(a0[mt][0], a0[mt][1], a0[mt][2], a0[mt][3], eb + ao);
            }
#pragma unroll
            for (int mt = 0; mt < 2; mt++)
#pragma unroll
                for (int nt = 0; nt < 4; nt++)
                    MMA16816(acc[mt][nt], a0[mt][0], a0[mt][1], a0[mt][2], a0[mt][3],
                             bw[ks][nt >> 1][(nt & 1) * 2], bw[ks][nt >> 1][(nt & 1) * 2 + 1]);
        }

        // ---- epilogue: gate with Q (gmem) and resident K (smem) -------------
        const float* qrow = g_Q + (size_t)bi * C_;
#pragma unroll
        for (int mt = 0; mt < 2; mt++) {
            const int r0 = m0 + mt * 16 + (lane >> 2);   // tile-local j
            const int r1 = r0 + 8;
            float* orow0 = out_e + (row_base + r0) * C_;
            float* orow1 = out_e + (row_base + r1) * C_;
            float hs0 = 0.f, hs1 = 0.f;
#pragma unroll
            for (int nt = 0; nt < 4; nt++) {
                int colp = n0 + nt * 8 + 2 * (lane & 3);
                float2 q2 = *(const float2*)(qrow + colp);
                float2 k0, k1;
                LDS64F(k0, sb + SM_K + (uint32_t)(r0 * 528 + colp * 4));
                LDS64F(k1, sb + SM_K + (uint32_t)(r1 * 528 + colp * 4));
                float2 e0, e1;
                e0.x = acc[mt][nt][0] * q2.x * k0.x;  e0.y = acc[mt][nt][1] * q2.y * k0.y;
                e1.x = acc[mt][nt][2] * q2.x * k1.x;  e1.y = acc[mt][nt][3] * q2.y * k1.y;
                __stcs((float2*)(orow0 + colp), e0);   // streaming: never re-read
                __stcs((float2*)(orow1 + colp), e1);
                hs0 += e0.x + e0.y;
                hs1 += e1.x + e1.y;
                if (nt & 1) {                        // head complete (2 n-tiles)
                    hs0 += __shfl_xor_sync(0xffffffffu, hs0, 1);
                    hs0 += __shfl_xor_sync(0xffffffffu, hs0, 2);
                    hs1 += __shfl_xor_sync(0xffffffffu, hs1, 1);
                    hs1 += __shfl_xor_sync(0xffffffffu, hs1, 2);
                    if ((lane & 3) == 0) {
                        int head = (n0 >> 4) + (nt >> 1);
                        float c0 = __expf(fminf(fmaxf(hs0, -5.f), 5.f));
                        float c1 = __expf(fminf(fmaxf(hs1, -5.f), 5.f));
                        float* sp = g_S + ((size_t)(b * H_ + head) * N_ + i) * N_ + j0;
                        sp[r0] = c0;
                        sp[r1] = c1;
                        cs[mt][nt >> 1][0] += c0;    // fold colsum
                        cs[mt][nt >> 1][1] += c1;
                    }
                    hs0 = 0.f; hs1 = 0.f;
                }
            }
        }

        // ---- cvt e(i+18) into the other fp16 buffer; issue e(i+36) ----------
        if (i + STRIDE_I < N_) {
            CP_WAIT0();
            cvt_stage(sb, sb + (p ? SM_E16A : SM_E16B), tid);
            if (i + 2 * STRIDE_I < N_) {
                cp_e_tile(sb, e, bi + 2 * STRIDE_I, j0, tid);
                CP_COMMIT();
            }
        }
        __syncthreads();   // single barrier: E16[p^1] handoff + tile retire
    }

    // ---- write colsum partials: g_cs2[w0][b*8+head][j0 + r] -----------------
    if ((lane & 3) == 0) {
#pragma unroll
        for (int mt = 0; mt < 2; mt++)
#pragma unroll
            for (int ntg = 0; ntg < 2; ntg++) {
                int head = (n0 >> 4) + ntg;
                int r0 = m0 + mt * 16 + (lane >> 2);
                float* cp = g_cs2 + ((size_t)w0 * 16 + b * H_ + head) * N_ + j0;
                cp[r0]     = cs[mt][ntg][0];
                cp[r0 + 8] = cs[mt][ntg][1];
            }
    }
}

// ============================================================================
// Kernel 3: h_out fused with softmax normalization.
// ============================================================================
__global__ void __launch_bounds__(256)
hout_kernel(float* __restrict__ out_h) {
    __shared__ float sV[N_ * 16];                  // 32 KB
    __shared__ float sInv[N_];
    int bh = blockIdx.x >> 5, i0 = (blockIdx.x & 31) << 4;
    int b = bh >> 3, head = bh & 7;
    int tid = threadIdx.x, ti = tid >> 4, c = tid & 15;

    for (int it = 0; it < 32; it++) {
        int q = tid + 256 * it;                    // 8192 floats
        int j = q >> 4, cc = q & 15;
        sV[q] = __ldg(g_V + ((size_t)b * N_ + j) * C_ + head * 16 + cc);
    }
    for (int tt = 0; tt < 2; tt++) {
        int j = tid + 256 * tt;
        float s = 0.f;
#pragma unroll
        for (int ch = 0; ch < STRIDE_I; ch++)
            s += g_cs2[((size_t)ch * 16 + bh) * N_ + j];
        sInv[j] = 1.f / s;
    }
    __syncthreads();

    int i = i0 + ti;
    const float4* prow = (const float4*)(g_S + ((size_t)bh * N_ + i) * N_);
    float acc = 0.f;
#pragma unroll 4
    for (int j4 = 0; j4 < 128; j4++) {
        float4 p = __ldg(prow + j4);
        int j = 4 * j4;
        acc += p.x * sInv[j]     * sV[(j)     * 16 + c];
        acc += p.y * sInv[j + 1] * sV[(j + 1) * 16 + c];
        acc += p.z * sInv[j + 2] * sV[(j + 2) * 16 + c];
        acc += p.w * sInv[j + 3] * sV[(j + 3) * 16 + c];
    }
    out_h[((size_t)b * N_ + i) * C_ + head * 16 + c] = acc;
}

// ============================================================================
extern "C" void kernel_launch(void* const* d_in, const int* in_sizes, int n_in,
                              void* d_out, int out_size) {
    const float* h  = (const float*)d_in[0];
    const float* e  = (const float*)d_in[1];
    const float* Wq = (const float*)d_in[2];
    const float* Wk = (const float*)d_in[3];
    const float* Wv = (const float*)d_in[4];
    const float* We = (const float*)d_in[5];

    float* out_h = (float*)d_out;                      // [B,N,C]
    float* out_e = (float*)d_out + B_ * N_ * C_;       // [B,N,N,C]

    cudaFuncSetAttribute(edge_kernel,
                         cudaFuncAttributeMaxDynamicSharedMemorySize, SM_TOT);

    prep_w_kernel<<<64, 256>>>(We);
    qkv_kernel<<<384, 256>>>(h, Wq, Wk, Wv);
    edge_kernel<<<16 * STRIDE_I, 256, SM_TOT>>>(e, out_e);
    hout_kernel<<<16 * 32, 256>>>(out_h);
}